// round 2
// baseline (speedup 1.0000x reference)
#include <cuda_runtime.h>
#include <cuda_bf16.h>
#include <math.h>

// ---------------------------------------------------------------------------
// Problem constants
// ---------------------------------------------------------------------------
#define Bz    8
#define Sz    8192
#define Nz    (Bz*Sz)          // 65536 tokens
#define Dz    512
#define Hz    8
#define HKz   2
#define DHz   64
#define Mz    64
#define Gz    (Hz/HKz)         // 4
#define DFFz  2048
#define NCLSz 2

// ---------------------------------------------------------------------------
// Scratch (device globals; no allocations allowed)
// ---------------------------------------------------------------------------
__device__ float d_x [Nz*Dz];        // residual stream
__device__ float d_h [Nz*Dz];        // rmsnorm output (reused for h2)
__device__ float d_q [Nz*Dz];        // q, later reused as attn output
__device__ float d_k [Nz*HKz*DHz];
__device__ float d_v [Nz*HKz*DHz];
__device__ float d_pq[Nz*Hz*Mz];
__device__ float d_pk[Nz*HKz*Mz];
__device__ float d_t1[(size_t)Nz*DFFz];  // FFN intermediate
__device__ float d_kv[Bz*HKz*Mz*DHz];    // global linear-attn state
__device__ float d_z [Bz*HKz*Mz];
__device__ float d_pool[Bz*Dz];

// ---------------------------------------------------------------------------
// Zero scratch accumulators (kv, z, pool)
// ---------------------------------------------------------------------------
__global__ void zero_scratch_kernel() {
    int i = blockIdx.x * 256 + threadIdx.x;
    if (i < Bz*HKz*Mz*DHz) d_kv[i]   = 0.f;
    if (i < Bz*HKz*Mz)     d_z[i]    = 0.f;
    if (i < Bz*Dz)         d_pool[i] = 0.f;
}

// ---------------------------------------------------------------------------
// Embedding gather + RMSNorm (writes x and h)
// grid: Nz blocks, 128 threads (4 floats each)
// ---------------------------------------------------------------------------
__global__ void embed_rms_kernel(const int* __restrict__ ids,
                                 const float* __restrict__ emb,
                                 const float* __restrict__ g) {
    int n   = blockIdx.x;
    int tid = threadIdx.x;
    int id  = ids[n];
    float4 v = *(const float4*)&emb[(size_t)id * Dz + tid * 4];
    float ss = v.x*v.x + v.y*v.y + v.z*v.z + v.w*v.w;
    __shared__ float red[4];
    #pragma unroll
    for (int o = 16; o; o >>= 1) ss += __shfl_xor_sync(0xffffffffu, ss, o);
    if ((tid & 31) == 0) red[tid >> 5] = ss;
    __syncthreads();
    float tot = red[0] + red[1] + red[2] + red[3];
    float scale = rsqrtf(tot / (float)Dz + 1e-6f);
    *(float4*)&d_x[(size_t)n * Dz + tid * 4] = v;
    float4 gv = *(const float4*)&g[tid * 4];
    float4 hv = make_float4(v.x*scale*gv.x, v.y*scale*gv.y,
                            v.z*scale*gv.z, v.w*scale*gv.w);
    *(float4*)&d_h[(size_t)n * Dz + tid * 4] = hv;
}

// RMSNorm of d_x into d_h (second pre-norm)
__global__ void rms_kernel(const float* __restrict__ g) {
    int n   = blockIdx.x;
    int tid = threadIdx.x;
    float4 v = *(const float4*)&d_x[(size_t)n * Dz + tid * 4];
    float ss = v.x*v.x + v.y*v.y + v.z*v.z + v.w*v.w;
    __shared__ float red[4];
    #pragma unroll
    for (int o = 16; o; o >>= 1) ss += __shfl_xor_sync(0xffffffffu, ss, o);
    if ((tid & 31) == 0) red[tid >> 5] = ss;
    __syncthreads();
    float tot = red[0] + red[1] + red[2] + red[3];
    float scale = rsqrtf(tot / (float)Dz + 1e-6f);
    float4 gv = *(const float4*)&g[tid * 4];
    float4 hv = make_float4(v.x*scale*gv.x, v.y*scale*gv.y,
                            v.z*scale*gv.z, v.w*scale*gv.w);
    *(float4*)&d_h[(size_t)n * Dz + tid * 4] = hv;
}

// ---------------------------------------------------------------------------
// Generic 128x128x8 register-tiled SGEMM with fused epilogues.
// A [Mr,K] row-major, B [K,Nc] row-major, C [Mr,Nc].
// MODE 0: C = acc
// MODE 1: C += acc            (residual add)
// MODE 2: C = silu(acc)
// MODE 3: C = C * acc         (SwiGLU multiply, in place)
// Requires: Mr % 128 == 0, Nc % 128 == 0, K % 8 == 0.
// grid: (Nc/128, Mr/128), block 256
// ---------------------------------------------------------------------------
template<int MODE>
__global__ void __launch_bounds__(256)
sgemm_kernel(const float* __restrict__ A, const float* __restrict__ B,
             float* __restrict__ C, int K, int Nc) {
    __shared__ float As[8][128];
    __shared__ float Bs[8][128];
    int tid = threadIdx.x;
    int tr = tid >> 4;         // 0..15
    int tc = tid & 15;         // 0..15
    const float* Aptr = A + (size_t)(blockIdx.y * 128) * K;
    const float* Bptr = B + (size_t)(blockIdx.x * 128);

    float acc[8][8];
    #pragma unroll
    for (int i = 0; i < 8; i++)
        #pragma unroll
        for (int j = 0; j < 8; j++) acc[i][j] = 0.f;

    int ar = tid >> 1, ac = (tid & 1) * 4;
    int br = tid >> 5, bc = (tid & 31) * 4;

    for (int k0 = 0; k0 < K; k0 += 8) {
        float4 av = *(const float4*)(Aptr + (size_t)ar * K + k0 + ac);
        As[ac+0][ar] = av.x; As[ac+1][ar] = av.y;
        As[ac+2][ar] = av.z; As[ac+3][ar] = av.w;
        float4 bv = *(const float4*)(Bptr + (size_t)(k0 + br) * Nc + bc);
        *(float4*)&Bs[br][bc] = bv;
        __syncthreads();
        #pragma unroll
        for (int kk = 0; kk < 8; kk++) {
            float4 a0 = *(const float4*)&As[kk][tr*8];
            float4 a1 = *(const float4*)&As[kk][tr*8+4];
            float4 b0 = *(const float4*)&Bs[kk][tc*8];
            float4 b1 = *(const float4*)&Bs[kk][tc*8+4];
            float ra[8] = {a0.x,a0.y,a0.z,a0.w,a1.x,a1.y,a1.z,a1.w};
            float rb[8] = {b0.x,b0.y,b0.z,b0.w,b1.x,b1.y,b1.z,b1.w};
            #pragma unroll
            for (int i = 0; i < 8; i++)
                #pragma unroll
                for (int j = 0; j < 8; j++)
                    acc[i][j] += ra[i] * rb[j];
        }
        __syncthreads();
    }

    int row0 = blockIdx.y * 128 + tr * 8;
    int col0 = blockIdx.x * 128 + tc * 8;
    #pragma unroll
    for (int i = 0; i < 8; i++) {
        size_t off = (size_t)(row0 + i) * Nc + col0;
        float4 v0 = make_float4(acc[i][0], acc[i][1], acc[i][2], acc[i][3]);
        float4 v1 = make_float4(acc[i][4], acc[i][5], acc[i][6], acc[i][7]);
        if (MODE == 1) {
            float4 c0 = *(float4*)&C[off];
            float4 c1 = *(float4*)&C[off + 4];
            v0.x += c0.x; v0.y += c0.y; v0.z += c0.z; v0.w += c0.w;
            v1.x += c1.x; v1.y += c1.y; v1.z += c1.z; v1.w += c1.w;
        } else if (MODE == 2) {
            v0.x = v0.x / (1.f + expf(-v0.x)); v0.y = v0.y / (1.f + expf(-v0.y));
            v0.z = v0.z / (1.f + expf(-v0.z)); v0.w = v0.w / (1.f + expf(-v0.w));
            v1.x = v1.x / (1.f + expf(-v1.x)); v1.y = v1.y / (1.f + expf(-v1.y));
            v1.z = v1.z / (1.f + expf(-v1.z)); v1.w = v1.w / (1.f + expf(-v1.w));
        } else if (MODE == 3) {
            float4 c0 = *(float4*)&C[off];
            float4 c1 = *(float4*)&C[off + 4];
            v0.x *= c0.x; v0.y *= c0.y; v0.z *= c0.z; v0.w *= c0.w;
            v1.x *= c1.x; v1.y *= c1.y; v1.z *= c1.z; v1.w *= c1.w;
        }
        *(float4*)&C[off]     = v0;
        *(float4*)&C[off + 4] = v1;
    }
}

// ---------------------------------------------------------------------------
// phi projection: out[n, h*64+m] = exp(-|sum_d in[n, h*64+d]*Wphi[d,m]|)
// grid: (Nz/64, heads), block 256
// ---------------------------------------------------------------------------
__global__ void phi_kernel(const float* __restrict__ in,
                           const float* __restrict__ Wphi,
                           float* __restrict__ out, int ld) {
    int h  = blockIdx.y;
    int n0 = blockIdx.x * 64;
    __shared__ float Ws[64][65];
    __shared__ float Qs[64][65];
    int tid = threadIdx.x;
    for (int i = tid; i < 4096; i += 256) {
        int r = i >> 6, c = i & 63;
        Ws[r][c] = Wphi[i];
        Qs[r][c] = in[(size_t)(n0 + r) * ld + h * 64 + c];
    }
    __syncthreads();
    int r  = tid >> 2;
    int m0 = (tid & 3) * 16;
    float acc[16];
    #pragma unroll
    for (int j = 0; j < 16; j++) acc[j] = 0.f;
    #pragma unroll 8
    for (int d = 0; d < 64; d++) {
        float qv = Qs[r][d];
        #pragma unroll
        for (int j = 0; j < 16; j++) acc[j] += qv * Ws[d][m0 + j];
    }
    size_t base = (size_t)(n0 + r) * ld + h * 64 + m0;
    #pragma unroll
    for (int j = 0; j < 16; j++)
        out[base + j] = expf(-fabsf(acc[j]));
}

// ---------------------------------------------------------------------------
// kv state reduction: kv[b,hk,m,d] = sum_s pk * v;  z[b,hk,m] = sum_s pk
// grid: (B*HK, 16 chunks of 512 tokens), block 256
// ---------------------------------------------------------------------------
__global__ void kv_reduce_kernel() {
    int bh = blockIdx.x;             // 0..15
    int b  = bh >> 1, hk = bh & 1;
    int s0 = blockIdx.y * 512;
    __shared__ float pks[8][64];
    __shared__ float vs [8][64];
    int tid = threadIdx.x;
    int m  = tid >> 2;
    int d0 = (tid & 3) * 16;
    float acc[16];
    #pragma unroll
    for (int j = 0; j < 16; j++) acc[j] = 0.f;
    float zacc = 0.f;
    int rr = tid >> 6;               // 0..3
    int cc = tid & 63;
    for (int ss = 0; ss < 512; ss += 8) {
        size_t n = (size_t)b * Sz + s0 + ss;
        pks[rr  ][cc] = d_pk[(n + rr    ) * (HKz*Mz) + hk*Mz + cc];
        pks[rr+4][cc] = d_pk[(n + rr + 4) * (HKz*Mz) + hk*Mz + cc];
        vs [rr  ][cc] = d_v [(n + rr    ) * (HKz*DHz) + hk*DHz + cc];
        vs [rr+4][cc] = d_v [(n + rr + 4) * (HKz*DHz) + hk*DHz + cc];
        __syncthreads();
        #pragma unroll
        for (int t = 0; t < 8; t++) {
            float pm = pks[t][m];
            zacc += pm;
            #pragma unroll
            for (int j = 0; j < 16; j++) acc[j] += pm * vs[t][d0 + j];
        }
        __syncthreads();
    }
    size_t base = ((size_t)bh * Mz + m) * DHz + d0;
    #pragma unroll
    for (int j = 0; j < 16; j++) atomicAdd(&d_kv[base + j], acc[j]);
    if ((tid & 3) == 0) atomicAdd(&d_z[bh * Mz + m], zacc);
}

// ---------------------------------------------------------------------------
// Attention readout: attn[n, h*64+d] = (pq . kv) / (pq . z + eps) -> d_q
// grid: Nz/32 blocks, 256 threads
// ---------------------------------------------------------------------------
__global__ void attn_kernel() {
    int n0 = blockIdx.x * 32;
    int b  = n0 >> 13;                  // / Sz
    __shared__ float kvs[2][64][64];
    __shared__ float zs [2][64];
    __shared__ float pqs[32][64];
    __shared__ float dens[32];
    int tid = threadIdx.x;
    for (int i = tid; i < 2*64*64; i += 256)
        ((float*)kvs)[i] = d_kv[(size_t)b * (HKz*Mz*DHz) + i];
    for (int i = tid; i < 2*64; i += 256)
        ((float*)zs)[i] = d_z[b * (HKz*Mz) + i];

    for (int h = 0; h < Hz; h++) {
        int hk = h >> 2;
        for (int i = tid; i < 32*64; i += 256) {
            int r = i >> 6, m = i & 63;
            pqs[r][m] = d_pq[(size_t)(n0 + r) * (Hz*Mz) + h*Mz + m];
        }
        __syncthreads();
        if (tid < 32) {
            float s = 0.f;
            #pragma unroll 8
            for (int m = 0; m < 64; m++) s += pqs[tid][m] * zs[hk][m];
            dens[tid] = s + 1e-6f;
        }
        __syncthreads();
        int r = tid >> 3, d0 = (tid & 7) * 8;
        float acc[8];
        #pragma unroll
        for (int j = 0; j < 8; j++) acc[j] = 0.f;
        #pragma unroll 8
        for (int m = 0; m < 64; m++) {
            float p = pqs[r][m];
            float4 k0 = *(float4*)&kvs[hk][m][d0];
            float4 k1 = *(float4*)&kvs[hk][m][d0 + 4];
            acc[0] += p*k0.x; acc[1] += p*k0.y; acc[2] += p*k0.z; acc[3] += p*k0.w;
            acc[4] += p*k1.x; acc[5] += p*k1.y; acc[6] += p*k1.z; acc[7] += p*k1.w;
        }
        float inv = 1.f / dens[r];
        size_t base = (size_t)(n0 + r) * (Hz*DHz) + h*DHz + d0;
        #pragma unroll
        for (int j = 0; j < 8; j++) d_q[base + j] = acc[j] * inv;
        __syncthreads();
    }
}

// ---------------------------------------------------------------------------
// Mean pool partials: pool[b,d] += sum over 512-token chunk of x
// grid (B, Dz/256, Sz/512), block 256
// ---------------------------------------------------------------------------
__global__ void pool_kernel() {
    int b = blockIdx.x;
    int d = blockIdx.y * 256 + threadIdx.x;
    size_t base = ((size_t)b * Sz + blockIdx.z * 512) * Dz + d;
    float s = 0.f;
    #pragma unroll 4
    for (int i = 0; i < 512; i++) s += d_x[base + (size_t)i * Dz];
    atomicAdd(&d_pool[b * Dz + d], s);
}

// ---------------------------------------------------------------------------
// Head: logits[b,c] = pool[b,:].Wc[:,c] / S + bc[c]
// 1 block, 512 threads (16 warps, one per (b,c))
// ---------------------------------------------------------------------------
__global__ void head_kernel(const float* __restrict__ Wc,
                            const float* __restrict__ bc,
                            float* __restrict__ out) {
    int w = threadIdx.x >> 5, lane = threadIdx.x & 31;
    int b = w >> 1, c = w & 1;
    float s = 0.f;
    for (int d = lane; d < Dz; d += 32)
        s += d_pool[b * Dz + d] * Wc[d * NCLSz + c];
    #pragma unroll
    for (int o = 16; o; o >>= 1) s += __shfl_xor_sync(0xffffffffu, s, o);
    if (lane == 0) out[b * NCLSz + c] = s / (float)Sz + bc[c];
}

// ---------------------------------------------------------------------------
// Launch. cudaGetSymbolAddress enqueues no stream work and is legal under
// graph capture; all actual work is plain kernel launches on the capture
// stream (no syncs, no allocations, no memcpies).
// ---------------------------------------------------------------------------
extern "C" void kernel_launch(void* const* d_in, const int* in_sizes, int n_in,
                              void* d_out, int out_size) {
    const int*   ids  = (const int*)  d_in[0];
    const float* emb  = (const float*)d_in[1];
    const float* Wq   = (const float*)d_in[2];
    const float* Wk   = (const float*)d_in[3];
    const float* Wv   = (const float*)d_in[4];
    const float* Wphi = (const float*)d_in[5];
    const float* Wo   = (const float*)d_in[6];
    const float* g1   = (const float*)d_in[7];
    const float* g2   = (const float*)d_in[8];
    const float* Wg   = (const float*)d_in[9];
    const float* Wu   = (const float*)d_in[10];
    const float* Wd   = (const float*)d_in[11];
    const float* Wc   = (const float*)d_in[12];
    const float* bc   = (const float*)d_in[13];
    float* out = (float*)d_out;

    float *px, *ph, *pq_, *pk_, *pv_, *ppq, *ppk, *pt1;
    cudaGetSymbolAddress((void**)&px,  d_x);
    cudaGetSymbolAddress((void**)&ph,  d_h);
    cudaGetSymbolAddress((void**)&pq_, d_q);
    cudaGetSymbolAddress((void**)&pk_, d_k);
    cudaGetSymbolAddress((void**)&pv_, d_v);
    cudaGetSymbolAddress((void**)&ppq, d_pq);
    cudaGetSymbolAddress((void**)&ppk, d_pk);
    cudaGetSymbolAddress((void**)&pt1, d_t1);

    // 1. zero accumulators
    zero_scratch_kernel<<<(Bz*HKz*Mz*DHz + 255)/256, 256>>>();
    // 2. embed + rmsnorm
    embed_rms_kernel<<<Nz, 128>>>(ids, emb, g1);
    // 3-5. QKV projections
    sgemm_kernel<0><<<dim3(Dz/128,        Nz/128), 256>>>(ph, Wq, pq_, Dz, Dz);
    sgemm_kernel<0><<<dim3(HKz*DHz/128,   Nz/128), 256>>>(ph, Wk, pk_, Dz, HKz*DHz);
    sgemm_kernel<0><<<dim3(HKz*DHz/128,   Nz/128), 256>>>(ph, Wv, pv_, Dz, HKz*DHz);
    // 6-7. Laplacian feature maps
    phi_kernel<<<dim3(Nz/64, Hz),  256>>>(pq_, Wphi, ppq, Hz*Mz);
    phi_kernel<<<dim3(Nz/64, HKz), 256>>>(pk_, Wphi, ppk, HKz*Mz);
    // 8. global state
    kv_reduce_kernel<<<dim3(Bz*HKz, 16), 256>>>();
    // 9. attention readout (into d_q)
    attn_kernel<<<Nz/32, 256>>>();
    // 10. x += attn @ Wo
    sgemm_kernel<1><<<dim3(Dz/128, Nz/128), 256>>>(pq_, Wo, px, Dz, Dz);
    // 11. h2 = rmsnorm(x, g2)
    rms_kernel<<<Nz, 128>>>(g2);
    // 12. t1 = silu(h2 @ Wg)
    sgemm_kernel<2><<<dim3(DFFz/128, Nz/128), 256>>>(ph, Wg, pt1, Dz, DFFz);
    // 13. t1 *= h2 @ Wu
    sgemm_kernel<3><<<dim3(DFFz/128, Nz/128), 256>>>(ph, Wu, pt1, Dz, DFFz);
    // 14. x += t1 @ Wd
    sgemm_kernel<1><<<dim3(Dz/128, Nz/128), 256>>>(pt1, Wd, px, DFFz, Dz);
    // 15. mean pool
    pool_kernel<<<dim3(Bz, Dz/256, Sz/512), 256>>>();
    // 16. head
    head_kernel<<<1, 512>>>(Wc, bc, out);
}

// round 4
// speedup vs baseline: 2.1697x; 2.1697x over previous
#include <cuda_runtime.h>
#include <cuda_bf16.h>
#include <math.h>

// ---------------------------------------------------------------------------
// Problem constants
// ---------------------------------------------------------------------------
#define Bz    8
#define Sz    8192
#define Nz    (Bz*Sz)          // 65536 tokens
#define Dz    512
#define Hz    8
#define HKz   2
#define DHz   64
#define Mz    64
#define Gz    (Hz/HKz)         // 4
#define DFFz  2048
#define NCLSz 2

// ---------------------------------------------------------------------------
// Scratch (device globals; no allocations allowed)
// ---------------------------------------------------------------------------
__device__ float d_x [Nz*Dz];        // residual stream
__device__ float d_h [Nz*Dz];        // rmsnorm output (reused for h2)
__device__ float d_q [Nz*Dz];        // q, later reused as attn output
__device__ float d_k [Nz*HKz*DHz];
__device__ float d_v [Nz*HKz*DHz];
__device__ float d_pq[Nz*Hz*Mz];
__device__ float d_pk[Nz*HKz*Mz];
__device__ float d_t1[(size_t)Nz*DFFz];  // FFN intermediate
__device__ float d_kv[Bz*HKz*Mz*DHz];    // global linear-attn state
__device__ float d_z [Bz*HKz*Mz];
__device__ float d_pool[Bz*Dz];

// ---------------------------------------------------------------------------
__global__ void zero_scratch_kernel() {
    int i = blockIdx.x * 256 + threadIdx.x;
    if (i < Bz*HKz*Mz*DHz) d_kv[i]   = 0.f;
    if (i < Bz*HKz*Mz)     d_z[i]    = 0.f;
    if (i < Bz*Dz)         d_pool[i] = 0.f;
}

// ---------------------------------------------------------------------------
// Embedding gather + RMSNorm (writes x and h)
// ---------------------------------------------------------------------------
__global__ void embed_rms_kernel(const int* __restrict__ ids,
                                 const float* __restrict__ emb,
                                 const float* __restrict__ g) {
    int n   = blockIdx.x;
    int tid = threadIdx.x;
    int id  = ids[n];
    float4 v = *(const float4*)&emb[(size_t)id * Dz + tid * 4];
    float ss = v.x*v.x + v.y*v.y + v.z*v.z + v.w*v.w;
    __shared__ float red[4];
    #pragma unroll
    for (int o = 16; o; o >>= 1) ss += __shfl_xor_sync(0xffffffffu, ss, o);
    if ((tid & 31) == 0) red[tid >> 5] = ss;
    __syncthreads();
    float tot = red[0] + red[1] + red[2] + red[3];
    float scale = rsqrtf(tot / (float)Dz + 1e-6f);
    *(float4*)&d_x[(size_t)n * Dz + tid * 4] = v;
    float4 gv = *(const float4*)&g[tid * 4];
    float4 hv = make_float4(v.x*scale*gv.x, v.y*scale*gv.y,
                            v.z*scale*gv.z, v.w*scale*gv.w);
    *(float4*)&d_h[(size_t)n * Dz + tid * 4] = hv;
}

// RMSNorm of d_x into d_h (second pre-norm)
__global__ void rms_kernel(const float* __restrict__ g) {
    int n   = blockIdx.x;
    int tid = threadIdx.x;
    float4 v = *(const float4*)&d_x[(size_t)n * Dz + tid * 4];
    float ss = v.x*v.x + v.y*v.y + v.z*v.z + v.w*v.w;
    __shared__ float red[4];
    #pragma unroll
    for (int o = 16; o; o >>= 1) ss += __shfl_xor_sync(0xffffffffu, ss, o);
    if ((tid & 31) == 0) red[tid >> 5] = ss;
    __syncthreads();
    float tot = red[0] + red[1] + red[2] + red[3];
    float scale = rsqrtf(tot / (float)Dz + 1e-6f);
    float4 gv = *(const float4*)&g[tid * 4];
    float4 hv = make_float4(v.x*scale*gv.x, v.y*scale*gv.y,
                            v.z*scale*gv.z, v.w*scale*gv.w);
    *(float4*)&d_h[(size_t)n * Dz + tid * 4] = hv;
}

// ---------------------------------------------------------------------------
// TF32 tensor-core GEMM, 128x128 tile, BK=16, double-buffered smem.
// A [Mr,K] row-major, B [K,Nc] row-major, C [Mr,Nc].
// MODE 0: C = acc;  1: C += acc;  2: C = silu(acc);  3: C = C * acc
// grid (Nc/128, Mr/128), block 256 (8 warps, each 64x32 via m16n8k8 tf32).
// ---------------------------------------------------------------------------
#define BKt  16
#define PADt 136   // padded smem row stride (floats): banks 8*(lane&3)+(lane>>2) all distinct

__device__ __forceinline__ float to_tf32(float x) {
    float r;
    asm("cvt.rna.tf32.f32 %0, %1;" : "=f"(r) : "f"(x));
    return r;
}

template<int MODE>
__global__ void __launch_bounds__(256)
tgemm_kernel(const float* __restrict__ A, const float* __restrict__ B,
             float* __restrict__ C, int K, int Nc) {
    __shared__ float As[2][BKt][PADt];   // [k][m]
    __shared__ float Bs[2][BKt][PADt];   // [k][n]
    int tid  = threadIdx.x;
    int lane = tid & 31;
    int warp = tid >> 5;
    int wm = (warp >> 2) * 64;           // 0 / 64
    int wn = (warp & 3) * 32;            // 0,32,64,96
    int gid = lane >> 2;                 // group id 0..7
    int tig = lane & 3;                  // thread in group 0..3

    const float* Aptr = A + (size_t)(blockIdx.y * 128) * K;
    const float* Bptr = B + blockIdx.x * 128;

    // global-load mapping
    int aRow = tid >> 1;                 // 0..127
    int aCol = (tid & 1) * 8;            // 0 or 8
    int bRow = tid >> 5;                 // 0..7 (and +8)
    int bCol = (tid & 31) * 4;

    float acc[4][4][4];
    #pragma unroll
    for (int i = 0; i < 4; i++)
        #pragma unroll
        for (int j = 0; j < 4; j++)
            #pragma unroll
            for (int r = 0; r < 4; r++) acc[i][j][r] = 0.f;

    float4 aR0, aR1, bR0, bR1;

    // prologue: load k0=0 tile
    aR0 = *(const float4*)(Aptr + (size_t)aRow * K + aCol);
    aR1 = *(const float4*)(Aptr + (size_t)aRow * K + aCol + 4);
    bR0 = *(const float4*)(Bptr + (size_t)bRow * Nc + bCol);
    bR1 = *(const float4*)(Bptr + (size_t)(bRow + 8) * Nc + bCol);
    {
        float av[8] = {aR0.x,aR0.y,aR0.z,aR0.w,aR1.x,aR1.y,aR1.z,aR1.w};
        #pragma unroll
        for (int i = 0; i < 8; i++) As[0][aCol + i][aRow] = to_tf32(av[i]);
        Bs[0][bRow  ][bCol+0] = to_tf32(bR0.x); Bs[0][bRow  ][bCol+1] = to_tf32(bR0.y);
        Bs[0][bRow  ][bCol+2] = to_tf32(bR0.z); Bs[0][bRow  ][bCol+3] = to_tf32(bR0.w);
        Bs[0][bRow+8][bCol+0] = to_tf32(bR1.x); Bs[0][bRow+8][bCol+1] = to_tf32(bR1.y);
        Bs[0][bRow+8][bCol+2] = to_tf32(bR1.z); Bs[0][bRow+8][bCol+3] = to_tf32(bR1.w);
    }
    __syncthreads();

    for (int k0 = 0; k0 < K; k0 += BKt) {
        int buf = (k0 / BKt) & 1;
        bool more = (k0 + BKt) < K;
        if (more) {
            aR0 = *(const float4*)(Aptr + (size_t)aRow * K + k0 + BKt + aCol);
            aR1 = *(const float4*)(Aptr + (size_t)aRow * K + k0 + BKt + aCol + 4);
            bR0 = *(const float4*)(Bptr + (size_t)(k0 + BKt + bRow) * Nc + bCol);
            bR1 = *(const float4*)(Bptr + (size_t)(k0 + BKt + bRow + 8) * Nc + bCol);
        }

        #pragma unroll
        for (int kk = 0; kk < BKt; kk += 8) {
            float a[4][4];
            #pragma unroll
            for (int mt = 0; mt < 4; mt++) {
                int r0 = wm + mt * 16 + gid;
                a[mt][0] = As[buf][kk + tig    ][r0];
                a[mt][1] = As[buf][kk + tig    ][r0 + 8];
                a[mt][2] = As[buf][kk + tig + 4][r0];
                a[mt][3] = As[buf][kk + tig + 4][r0 + 8];
            }
            float b[4][2];
            #pragma unroll
            for (int nt = 0; nt < 4; nt++) {
                int cn = wn + nt * 8 + gid;
                b[nt][0] = Bs[buf][kk + tig    ][cn];
                b[nt][1] = Bs[buf][kk + tig + 4][cn];
            }
            #pragma unroll
            for (int mt = 0; mt < 4; mt++)
                #pragma unroll
                for (int nt = 0; nt < 4; nt++) {
                    asm volatile(
                        "mma.sync.aligned.m16n8k8.row.col.f32.tf32.tf32.f32 "
                        "{%0,%1,%2,%3}, {%4,%5,%6,%7}, {%8,%9}, {%0,%1,%2,%3};"
                        : "+f"(acc[mt][nt][0]), "+f"(acc[mt][nt][1]),
                          "+f"(acc[mt][nt][2]), "+f"(acc[mt][nt][3])
                        : "r"(__float_as_uint(a[mt][0])), "r"(__float_as_uint(a[mt][1])),
                          "r"(__float_as_uint(a[mt][2])), "r"(__float_as_uint(a[mt][3])),
                          "r"(__float_as_uint(b[nt][0])), "r"(__float_as_uint(b[nt][1])));
                }
        }

        if (more) {
            int nb = buf ^ 1;
            float av[8] = {aR0.x,aR0.y,aR0.z,aR0.w,aR1.x,aR1.y,aR1.z,aR1.w};
            #pragma unroll
            for (int i = 0; i < 8; i++) As[nb][aCol + i][aRow] = to_tf32(av[i]);
            Bs[nb][bRow  ][bCol+0] = to_tf32(bR0.x); Bs[nb][bRow  ][bCol+1] = to_tf32(bR0.y);
            Bs[nb][bRow  ][bCol+2] = to_tf32(bR0.z); Bs[nb][bRow  ][bCol+3] = to_tf32(bR0.w);
            Bs[nb][bRow+8][bCol+0] = to_tf32(bR1.x); Bs[nb][bRow+8][bCol+1] = to_tf32(bR1.y);
            Bs[nb][bRow+8][bCol+2] = to_tf32(bR1.z); Bs[nb][bRow+8][bCol+3] = to_tf32(bR1.w);
        }
        __syncthreads();
    }

    // epilogue: c-frag rows gid,+8 ; cols tig*2, tig*2+1
    int rowBase = blockIdx.y * 128 + wm;
    int colBase = blockIdx.x * 128 + wn;
    #pragma unroll
    for (int mt = 0; mt < 4; mt++) {
        #pragma unroll
        for (int nt = 0; nt < 4; nt++) {
            #pragma unroll
            for (int half = 0; half < 2; half++) {
                int row = rowBase + mt * 16 + gid + half * 8;
                int col = colBase + nt * 8 + tig * 2;
                size_t off = (size_t)row * Nc + col;
                float v0 = acc[mt][nt][half * 2 + 0];
                float v1 = acc[mt][nt][half * 2 + 1];
                if (MODE == 1) {
                    float2 c = *(float2*)&C[off];
                    v0 += c.x; v1 += c.y;
                } else if (MODE == 2) {
                    v0 = v0 / (1.f + expf(-v0));
                    v1 = v1 / (1.f + expf(-v1));
                } else if (MODE == 3) {
                    float2 c = *(float2*)&C[off];
                    v0 *= c.x; v1 *= c.y;
                }
                float2 o; o.x = v0; o.y = v1;
                *(float2*)&C[off] = o;
            }
        }
    }
}

// ---------------------------------------------------------------------------
// phi projection: out[n, h*64+m] = exp(-|sum_d in[n, h*64+d]*Wphi[d,m]|)
// grid: (Nz/64, heads), block 256
// ---------------------------------------------------------------------------
__global__ void phi_kernel(const float* __restrict__ in,
                           const float* __restrict__ Wphi,
                           float* __restrict__ out, int ld) {
    int h  = blockIdx.y;
    int n0 = blockIdx.x * 64;
    __shared__ float Ws[64][65];
    __shared__ float Qs[64][65];
    int tid = threadIdx.x;
    for (int i = tid; i < 4096; i += 256) {
        int r = i >> 6, c = i & 63;
        Ws[r][c] = Wphi[i];
        Qs[r][c] = in[(size_t)(n0 + r) * ld + h * 64 + c];
    }
    __syncthreads();
    int r  = tid >> 2;
    int m0 = (tid & 3) * 16;
    float acc[16];
    #pragma unroll
    for (int j = 0; j < 16; j++) acc[j] = 0.f;
    #pragma unroll 8
    for (int d = 0; d < 64; d++) {
        float qv = Qs[r][d];
        #pragma unroll
        for (int j = 0; j < 16; j++) acc[j] += qv * Ws[d][m0 + j];
    }
    size_t base = (size_t)(n0 + r) * ld + h * 64 + m0;
    #pragma unroll
    for (int j = 0; j < 16; j++)
        out[base + j] = expf(-fabsf(acc[j]));
}

// ---------------------------------------------------------------------------
// kv state reduction: kv[b,hk,m,d] = sum_s pk * v;  z[b,hk,m] = sum_s pk
// grid: (B*HK, 16 chunks of 512 tokens), block 256
// ---------------------------------------------------------------------------
__global__ void kv_reduce_kernel() {
    int bh = blockIdx.x;             // 0..15
    int b  = bh >> 1, hk = bh & 1;
    int s0 = blockIdx.y * 512;
    __shared__ float pks[8][64];
    __shared__ float vs [8][64];
    int tid = threadIdx.x;
    int m  = tid >> 2;
    int d0 = (tid & 3) * 16;
    float acc[16];
    #pragma unroll
    for (int j = 0; j < 16; j++) acc[j] = 0.f;
    float zacc = 0.f;
    int rr = tid >> 6;               // 0..3
    int cc = tid & 63;
    for (int ss = 0; ss < 512; ss += 8) {
        size_t n = (size_t)b * Sz + s0 + ss;
        pks[rr  ][cc] = d_pk[(n + rr    ) * (HKz*Mz) + hk*Mz + cc];
        pks[rr+4][cc] = d_pk[(n + rr + 4) * (HKz*Mz) + hk*Mz + cc];
        vs [rr  ][cc] = d_v [(n + rr    ) * (HKz*DHz) + hk*DHz + cc];
        vs [rr+4][cc] = d_v [(n + rr + 4) * (HKz*DHz) + hk*DHz + cc];
        __syncthreads();
        #pragma unroll
        for (int t = 0; t < 8; t++) {
            float pm = pks[t][m];
            zacc += pm;
            #pragma unroll
            for (int j = 0; j < 16; j++) acc[j] += pm * vs[t][d0 + j];
        }
        __syncthreads();
    }
    size_t base = ((size_t)bh * Mz + m) * DHz + d0;
    #pragma unroll
    for (int j = 0; j < 16; j++) atomicAdd(&d_kv[base + j], acc[j]);
    if ((tid & 3) == 0) atomicAdd(&d_z[bh * Mz + m], zacc);
}

// ---------------------------------------------------------------------------
// Attention readout: attn[n, h*64+d] = (pq . kv) / (pq . z + eps) -> d_q
// grid: Nz/32 blocks, 256 threads
// ---------------------------------------------------------------------------
__global__ void attn_kernel() {
    int n0 = blockIdx.x * 32;
    int b  = n0 >> 13;                  // / Sz
    __shared__ float kvs[2][64][64];
    __shared__ float zs [2][64];
    __shared__ float pqs[32][64];
    __shared__ float dens[32];
    int tid = threadIdx.x;
    for (int i = tid; i < 2*64*64; i += 256)
        ((float*)kvs)[i] = d_kv[(size_t)b * (HKz*Mz*DHz) + i];
    for (int i = tid; i < 2*64; i += 256)
        ((float*)zs)[i] = d_z[b * (HKz*Mz) + i];

    for (int h = 0; h < Hz; h++) {
        int hk = h >> 2;
        for (int i = tid; i < 32*64; i += 256) {
            int r = i >> 6, m = i & 63;
            pqs[r][m] = d_pq[(size_t)(n0 + r) * (Hz*Mz) + h*Mz + m];
        }
        __syncthreads();
        if (tid < 32) {
            float s = 0.f;
            #pragma unroll 8
            for (int m = 0; m < 64; m++) s += pqs[tid][m] * zs[hk][m];
            dens[tid] = s + 1e-6f;
        }
        __syncthreads();
        int r = tid >> 3, d0 = (tid & 7) * 8;
        float acc[8];
        #pragma unroll
        for (int j = 0; j < 8; j++) acc[j] = 0.f;
        #pragma unroll 8
        for (int m = 0; m < 64; m++) {
            float p = pqs[r][m];
            float4 k0 = *(float4*)&kvs[hk][m][d0];
            float4 k1 = *(float4*)&kvs[hk][m][d0 + 4];
            acc[0] += p*k0.x; acc[1] += p*k0.y; acc[2] += p*k0.z; acc[3] += p*k0.w;
            acc[4] += p*k1.x; acc[5] += p*k1.y; acc[6] += p*k1.z; acc[7] += p*k1.w;
        }
        float inv = 1.f / dens[r];
        size_t base = (size_t)(n0 + r) * (Hz*DHz) + h*DHz + d0;
        #pragma unroll
        for (int j = 0; j < 8; j++) d_q[base + j] = acc[j] * inv;
        __syncthreads();
    }
}

// ---------------------------------------------------------------------------
// Mean pool partials
// ---------------------------------------------------------------------------
__global__ void pool_kernel() {
    int b = blockIdx.x;
    int d = blockIdx.y * 256 + threadIdx.x;
    size_t base = ((size_t)b * Sz + blockIdx.z * 512) * Dz + d;
    float s = 0.f;
    #pragma unroll 4
    for (int i = 0; i < 512; i++) s += d_x[base + (size_t)i * Dz];
    atomicAdd(&d_pool[b * Dz + d], s);
}

// ---------------------------------------------------------------------------
// Head
// ---------------------------------------------------------------------------
__global__ void head_kernel(const float* __restrict__ Wc,
                            const float* __restrict__ bc,
                            float* __restrict__ out) {
    int w = threadIdx.x >> 5, lane = threadIdx.x & 31;
    int b = w >> 1, c = w & 1;
    float s = 0.f;
    for (int d = lane; d < Dz; d += 32)
        s += d_pool[b * Dz + d] * Wc[d * NCLSz + c];
    #pragma unroll
    for (int o = 16; o; o >>= 1) s += __shfl_xor_sync(0xffffffffu, s, o);
    if (lane == 0) out[b * NCLSz + c] = s / (float)Sz + bc[c];
}

// ---------------------------------------------------------------------------
// Launch (graph-capturable: kernel launches only)
// ---------------------------------------------------------------------------
extern "C" void kernel_launch(void* const* d_in, const int* in_sizes, int n_in,
                              void* d_out, int out_size) {
    const int*   ids  = (const int*)  d_in[0];
    const float* emb  = (const float*)d_in[1];
    const float* Wq   = (const float*)d_in[2];
    const float* Wk   = (const float*)d_in[3];
    const float* Wv   = (const float*)d_in[4];
    const float* Wphi = (const float*)d_in[5];
    const float* Wo   = (const float*)d_in[6];
    const float* g1   = (const float*)d_in[7];
    const float* g2   = (const float*)d_in[8];
    const float* Wg   = (const float*)d_in[9];
    const float* Wu   = (const float*)d_in[10];
    const float* Wd   = (const float*)d_in[11];
    const float* Wc   = (const float*)d_in[12];
    const float* bc   = (const float*)d_in[13];
    float* out = (float*)d_out;

    float *px, *ph, *pq_, *pk_, *pv_, *ppq, *ppk, *pt1;
    cudaGetSymbolAddress((void**)&px,  d_x);
    cudaGetSymbolAddress((void**)&ph,  d_h);
    cudaGetSymbolAddress((void**)&pq_, d_q);
    cudaGetSymbolAddress((void**)&pk_, d_k);
    cudaGetSymbolAddress((void**)&pv_, d_v);
    cudaGetSymbolAddress((void**)&ppq, d_pq);
    cudaGetSymbolAddress((void**)&ppk, d_pk);
    cudaGetSymbolAddress((void**)&pt1, d_t1);

    // 1. zero accumulators
    zero_scratch_kernel<<<(Bz*HKz*Mz*DHz + 255)/256, 256>>>();
    // 2. embed + rmsnorm
    embed_rms_kernel<<<Nz, 128>>>(ids, emb, g1);
    // 3-5. QKV projections (tf32 tensor cores)
    tgemm_kernel<0><<<dim3(Dz/128,        Nz/128), 256>>>(ph, Wq, pq_, Dz, Dz);
    tgemm_kernel<0><<<dim3(HKz*DHz/128,   Nz/128), 256>>>(ph, Wk, pk_, Dz, HKz*DHz);
    tgemm_kernel<0><<<dim3(HKz*DHz/128,   Nz/128), 256>>>(ph, Wv, pv_, Dz, HKz*DHz);
    // 6-7. Laplacian feature maps
    phi_kernel<<<dim3(Nz/64, Hz),  256>>>(pq_, Wphi, ppq, Hz*Mz);
    phi_kernel<<<dim3(Nz/64, HKz), 256>>>(pk_, Wphi, ppk, HKz*Mz);
    // 8. global state
    kv_reduce_kernel<<<dim3(Bz*HKz, 16), 256>>>();
    // 9. attention readout (into d_q)
    attn_kernel<<<Nz/32, 256>>>();
    // 10. x += attn @ Wo
    tgemm_kernel<1><<<dim3(Dz/128, Nz/128), 256>>>(pq_, Wo, px, Dz, Dz);
    // 11. h2 = rmsnorm(x, g2)
    rms_kernel<<<Nz, 128>>>(g2);
    // 12. t1 = silu(h2 @ Wg)
    tgemm_kernel<2><<<dim3(DFFz/128, Nz/128), 256>>>(ph, Wg, pt1, Dz, DFFz);
    // 13. t1 *= h2 @ Wu
    tgemm_kernel<3><<<dim3(DFFz/128, Nz/128), 256>>>(ph, Wu, pt1, Dz, DFFz);
    // 14. x += t1 @ Wd
    tgemm_kernel<1><<<dim3(Dz/128, Nz/128), 256>>>(pt1, Wd, px, DFFz, Dz);
    // 15. mean pool
    pool_kernel<<<dim3(Bz, Dz/256, Sz/512), 256>>>();
    // 16. head
    head_kernel<<<1, 512>>>(Wc, bc, out);
}

// round 7
// speedup vs baseline: 2.1708x; 1.0005x over previous
#include <cuda_runtime.h>
#include <cuda_bf16.h>
#include <math.h>
#include <stdint.h>

// ---------------------------------------------------------------------------
// Problem constants
// ---------------------------------------------------------------------------
#define Bz    8
#define Sz    8192
#define Nz    (Bz*Sz)          // 65536 tokens
#define Dz    512
#define Hz    8
#define HKz   2
#define DHz   64
#define Mz    64
#define Gz    (Hz/HKz)         // 4
#define DFFz  2048
#define NCLSz 2

// ---------------------------------------------------------------------------
// Scratch (device globals; no allocations allowed)
// ---------------------------------------------------------------------------
__device__ float d_x [Nz*Dz];        // residual stream
__device__ float d_h [Nz*Dz];        // rmsnorm output (reused for h2), tf32
__device__ float d_q [Nz*Dz];        // q, later reused as attn output (tf32)
__device__ float d_k [Nz*HKz*DHz];
__device__ float d_v [Nz*HKz*DHz];
__device__ float d_pq[Nz*Hz*Mz];
__device__ float d_pk[Nz*HKz*Mz];
__device__ float d_t1[(size_t)Nz*DFFz];  // FFN intermediate (tf32 after MODE3)
__device__ float d_kv[Bz*HKz*Mz*DHz];    // global linear-attn state
__device__ float d_z [Bz*HKz*Mz];
__device__ float d_pool[Bz*Dz];
// tf32-rounded weights (original [K,N] layouts), packed:
// Wq@0(262144) Wk@262144(65536) Wv@327680(65536) Wo@393216(262144)
// Wg@655360(1048576) Wu@1703936(1048576) Wd@2752512(1048576)
__device__ float d_wt[3801088];

// ---------------------------------------------------------------------------
// helpers
// ---------------------------------------------------------------------------
__device__ __forceinline__ float to_tf32(float x) {
    float r;
    asm("cvt.rna.tf32.f32 %0, %1;" : "=f"(r) : "f"(x));
    return r;
}
__device__ __forceinline__ uint32_t smem_u32(const void* p) {
    uint32_t a;
    asm("{ .reg .u64 t; cvta.to.shared.u64 t, %1; cvt.u32.u64 %0, t; }"
        : "=r"(a) : "l"(p));
    return a;
}
__device__ __forceinline__ void cp16(uint32_t s, const void* g) {
    asm volatile("cp.async.cg.shared.global [%0], [%1], 16;" :: "r"(s), "l"(g));
}
#define CP_COMMIT() asm volatile("cp.async.commit_group;" ::: "memory")

// ---------------------------------------------------------------------------
__global__ void zero_scratch_kernel() {
    int i = blockIdx.x * 256 + threadIdx.x;
    if (i < Bz*HKz*Mz*DHz) d_kv[i]   = 0.f;
    if (i < Bz*HKz*Mz)     d_z[i]    = 0.f;
    if (i < Bz*Dz)         d_pool[i] = 0.f;
}

// tf32-round copy of weights (layout preserved)
__global__ void round_copy_kernel(const float* __restrict__ src,
                                  float* __restrict__ dst, int n4) {
    int i = blockIdx.x * 256 + threadIdx.x;
    if (i < n4) {
        float4 v = ((const float4*)src)[i];
        v.x = to_tf32(v.x); v.y = to_tf32(v.y);
        v.z = to_tf32(v.z); v.w = to_tf32(v.w);
        ((float4*)dst)[i] = v;
    }
}

// ---------------------------------------------------------------------------
// Embedding gather + RMSNorm (x fp32, h tf32-rounded)
// ---------------------------------------------------------------------------
__global__ void embed_rms_kernel(const int* __restrict__ ids,
                                 const float* __restrict__ emb,
                                 const float* __restrict__ g) {
    int n   = blockIdx.x;
    int tid = threadIdx.x;
    int id  = ids[n];
    float4 v = *(const float4*)&emb[(size_t)id * Dz + tid * 4];
    float ss = v.x*v.x + v.y*v.y + v.z*v.z + v.w*v.w;
    __shared__ float red[4];
    #pragma unroll
    for (int o = 16; o; o >>= 1) ss += __shfl_xor_sync(0xffffffffu, ss, o);
    if ((tid & 31) == 0) red[tid >> 5] = ss;
    __syncthreads();
    float tot = red[0] + red[1] + red[2] + red[3];
    float scale = rsqrtf(tot / (float)Dz + 1e-6f);
    *(float4*)&d_x[(size_t)n * Dz + tid * 4] = v;
    float4 gv = *(const float4*)&g[tid * 4];
    float4 hv = make_float4(to_tf32(v.x*scale*gv.x), to_tf32(v.y*scale*gv.y),
                            to_tf32(v.z*scale*gv.z), to_tf32(v.w*scale*gv.w));
    *(float4*)&d_h[(size_t)n * Dz + tid * 4] = hv;
}

// RMSNorm of d_x into d_h (second pre-norm), tf32-rounded
__global__ void rms_kernel(const float* __restrict__ g) {
    int n   = blockIdx.x;
    int tid = threadIdx.x;
    float4 v = *(const float4*)&d_x[(size_t)n * Dz + tid * 4];
    float ss = v.x*v.x + v.y*v.y + v.z*v.z + v.w*v.w;
    __shared__ float red[4];
    #pragma unroll
    for (int o = 16; o; o >>= 1) ss += __shfl_xor_sync(0xffffffffu, ss, o);
    if ((tid & 31) == 0) red[tid >> 5] = ss;
    __syncthreads();
    float tot = red[0] + red[1] + red[2] + red[3];
    float scale = rsqrtf(tot / (float)Dz + 1e-6f);
    float4 gv = *(const float4*)&g[tid * 4];
    float4 hv = make_float4(to_tf32(v.x*scale*gv.x), to_tf32(v.y*scale*gv.y),
                            to_tf32(v.z*scale*gv.z), to_tf32(v.w*scale*gv.w));
    *(float4*)&d_h[(size_t)n * Dz + tid * 4] = hv;
}

// ---------------------------------------------------------------------------
// TF32 mma.sync GEMM v2: block tile 256x128, warp tile 64x64 (8 warps 4x2),
// BK=16, 3-stage cp.async pipeline. Inputs must be tf32-pre-rounded.
// A [Mr,K] row-major, B [K,Nc] row-major, C [Mr,Nc].
// MODE 0: C=acc; 1: C+=acc; 2: C=silu(acc); 3: C=tf32(C*acc).
// grid (Nc/128, Mr/256), block 256, dynamic smem 87552 B.
// ---------------------------------------------------------------------------
#define APADf 20      // floats per A smem row ([m][k] layout, 16 k + 4 pad)
#define BPADf 136     // floats per B smem row ([k][n] layout, 128 n + 8 pad)
#define ASTGf (256*APADf)   // 5120 floats / stage
#define BSTGf (16*BPADf)    // 2176 floats / stage
#define NSTG  3

template<int MODE>
__global__ void __launch_bounds__(256)
tgemm2_kernel(const float* __restrict__ A, const float* __restrict__ B,
              float* __restrict__ C, int K, int Nc) {
    extern __shared__ float sm[];
    float* As = sm;                       // [3][256][APADf]
    float* Bs = sm + NSTG * ASTGf;        // [3][16][BPADf]
    uint32_t uA = smem_u32(As);
    uint32_t uB = smem_u32(Bs);

    int tid  = threadIdx.x;
    int lane = tid & 31;
    int warp = tid >> 5;
    int wm  = (warp >> 1) * 64;           // 0,64,128,192
    int wn  = (warp & 1) * 64;            // 0,64
    int gid = lane >> 2;                  // 0..7
    int tig = lane & 3;                   // 0..3

    const float* Ablk = A + (size_t)(blockIdx.y * 256) * K;
    const float* Bblk = B + blockIdx.x * 128;

    float acc[4][8][4];
    #pragma unroll
    for (int i = 0; i < 4; i++)
        #pragma unroll
        for (int j = 0; j < 8; j++)
            #pragma unroll
            for (int r = 0; r < 4; r++) acc[i][j][r] = 0.f;

    // per-thread copy coordinates
    int am = tid >> 2, ac = (tid & 3) * 4;          // A: 4 chunks (m += 64)
    int bk = tid >> 5, bn = (tid & 31) * 4;         // B: 2 chunks (k += 8)

    int NS = K >> 4;

    // stage loader
    auto load_stage = [&](int s, int buf) {
        int k0 = s << 4;
        uint32_t ab = uA + (uint32_t)buf * (ASTGf * 4);
        uint32_t bb = uB + (uint32_t)buf * (BSTGf * 4);
        #pragma unroll
        for (int t = 0; t < 4; t++) {
            int m = am + t * 64;
            cp16(ab + (uint32_t)(m * APADf + ac) * 4,
                 Ablk + (size_t)m * K + k0 + ac);
        }
        #pragma unroll
        for (int t = 0; t < 2; t++) {
            int k = bk + t * 8;
            cp16(bb + (uint32_t)(k * BPADf + bn) * 4,
                 Bblk + (size_t)(k0 + k) * Nc + bn);
        }
        CP_COMMIT();
    };

    load_stage(0, 0);
    load_stage(1, 1);

    int bufC = 0, bufL = 2;
    for (int s = 0; s < NS; s++) {
        if (s + 2 < NS) load_stage(s + 2, bufL);
        if (s + 2 < NS)      asm volatile("cp.async.wait_group 2;" ::: "memory");
        else if (s + 1 < NS) asm volatile("cp.async.wait_group 1;" ::: "memory");
        else                 asm volatile("cp.async.wait_group 0;" ::: "memory");
        __syncthreads();

        const float* Ab = As + bufC * ASTGf;
        const float* Bb = Bs + bufC * BSTGf;
        #pragma unroll
        for (int kk = 0; kk < 16; kk += 8) {
            float a[4][4];
            #pragma unroll
            for (int mt = 0; mt < 4; mt++) {
                int r0 = wm + mt * 16 + gid;
                a[mt][0] = Ab[r0 * APADf + kk + tig];
                a[mt][1] = Ab[(r0 + 8) * APADf + kk + tig];
                a[mt][2] = Ab[r0 * APADf + kk + tig + 4];
                a[mt][3] = Ab[(r0 + 8) * APADf + kk + tig + 4];
            }
            float b[8][2];
            #pragma unroll
            for (int nt = 0; nt < 8; nt++) {
                int cn = wn + nt * 8 + gid;
                b[nt][0] = Bb[(kk + tig) * BPADf + cn];
                b[nt][1] = Bb[(kk + tig + 4) * BPADf + cn];
            }
            #pragma unroll
            for (int mt = 0; mt < 4; mt++)
                #pragma unroll
                for (int nt = 0; nt < 8; nt++) {
                    asm volatile(
                        "mma.sync.aligned.m16n8k8.row.col.f32.tf32.tf32.f32 "
                        "{%0,%1,%2,%3}, {%4,%5,%6,%7}, {%8,%9}, {%0,%1,%2,%3};"
                        : "+f"(acc[mt][nt][0]), "+f"(acc[mt][nt][1]),
                          "+f"(acc[mt][nt][2]), "+f"(acc[mt][nt][3])
                        : "r"(__float_as_uint(a[mt][0])), "r"(__float_as_uint(a[mt][1])),
                          "r"(__float_as_uint(a[mt][2])), "r"(__float_as_uint(a[mt][3])),
                          "r"(__float_as_uint(b[nt][0])), "r"(__float_as_uint(b[nt][1])));
                }
        }
        __syncthreads();
        bufC++; if (bufC == NSTG) bufC = 0;
        bufL++; if (bufL == NSTG) bufL = 0;
    }

    // epilogue
    int rowBase = blockIdx.y * 256 + wm;
    int colBase = blockIdx.x * 128 + wn;
    #pragma unroll
    for (int mt = 0; mt < 4; mt++) {
        #pragma unroll
        for (int nt = 0; nt < 8; nt++) {
            #pragma unroll
            for (int half = 0; half < 2; half++) {
                int row = rowBase + mt * 16 + gid + half * 8;
                int col = colBase + nt * 8 + tig * 2;
                size_t off = (size_t)row * Nc + col;
                float v0 = acc[mt][nt][half * 2 + 0];
                float v1 = acc[mt][nt][half * 2 + 1];
                if (MODE == 1) {
                    float2 c = *(float2*)&C[off];
                    v0 += c.x; v1 += c.y;
                } else if (MODE == 2) {
                    v0 = v0 / (1.f + expf(-v0));
                    v1 = v1 / (1.f + expf(-v1));
                } else if (MODE == 3) {
                    float2 c = *(float2*)&C[off];
                    v0 = to_tf32(v0 * c.x); v1 = to_tf32(v1 * c.y);
                }
                float2 o; o.x = v0; o.y = v1;
                *(float2*)&C[off] = o;
            }
        }
    }
}

// ---------------------------------------------------------------------------
// phi projection: out[n, h*64+m] = exp(-|sum_d in[n, h*64+d]*Wphi[d,m]|)
// ---------------------------------------------------------------------------
__global__ void phi_kernel(const float* __restrict__ in,
                           const float* __restrict__ Wphi,
                           float* __restrict__ out, int ld) {
    int h  = blockIdx.y;
    int n0 = blockIdx.x * 64;
    __shared__ float Ws[64][65];
    __shared__ float Qs[64][65];
    int tid = threadIdx.x;
    for (int i = tid; i < 4096; i += 256) {
        int r = i >> 6, c = i & 63;
        Ws[r][c] = Wphi[i];
        Qs[r][c] = in[(size_t)(n0 + r) * ld + h * 64 + c];
    }
    __syncthreads();
    int r  = tid >> 2;
    int m0 = (tid & 3) * 16;
    float acc[16];
    #pragma unroll
    for (int j = 0; j < 16; j++) acc[j] = 0.f;
    #pragma unroll 8
    for (int d = 0; d < 64; d++) {
        float qv = Qs[r][d];
        #pragma unroll
        for (int j = 0; j < 16; j++) acc[j] += qv * Ws[d][m0 + j];
    }
    size_t base = (size_t)(n0 + r) * ld + h * 64 + m0;
    #pragma unroll
    for (int j = 0; j < 16; j++)
        out[base + j] = expf(-fabsf(acc[j]));
}

// ---------------------------------------------------------------------------
// kv state reduction: kv[b,hk,m,d] = sum_s pk * v;  z[b,hk,m] = sum_s pk
// ---------------------------------------------------------------------------
__global__ void kv_reduce_kernel() {
    int bh = blockIdx.x;             // 0..15
    int b  = bh >> 1, hk = bh & 1;
    int s0 = blockIdx.y * 512;
    __shared__ float pks[8][64];
    __shared__ float vs [8][64];
    int tid = threadIdx.x;
    int m  = tid >> 2;
    int d0 = (tid & 3) * 16;
    float acc[16];
    #pragma unroll
    for (int j = 0; j < 16; j++) acc[j] = 0.f;
    float zacc = 0.f;
    int rr = tid >> 6;               // 0..3
    int cc = tid & 63;
    for (int ss = 0; ss < 512; ss += 8) {
        size_t n = (size_t)b * Sz + s0 + ss;
        pks[rr  ][cc] = d_pk[(n + rr    ) * (HKz*Mz) + hk*Mz + cc];
        pks[rr+4][cc] = d_pk[(n + rr + 4) * (HKz*Mz) + hk*Mz + cc];
        vs [rr  ][cc] = d_v [(n + rr    ) * (HKz*DHz) + hk*DHz + cc];
        vs [rr+4][cc] = d_v [(n + rr + 4) * (HKz*DHz) + hk*DHz + cc];
        __syncthreads();
        #pragma unroll
        for (int t = 0; t < 8; t++) {
            float pm = pks[t][m];
            zacc += pm;
            #pragma unroll
            for (int j = 0; j < 16; j++) acc[j] += pm * vs[t][d0 + j];
        }
        __syncthreads();
    }
    size_t base = ((size_t)bh * Mz + m) * DHz + d0;
    #pragma unroll
    for (int j = 0; j < 16; j++) atomicAdd(&d_kv[base + j], acc[j]);
    if ((tid & 3) == 0) atomicAdd(&d_z[bh * Mz + m], zacc);
}

// ---------------------------------------------------------------------------
// Attention readout: attn[n, h*64+d] = (pq . kv)/(pq . z + eps) -> d_q (tf32)
// ---------------------------------------------------------------------------
__global__ void attn_kernel() {
    int n0 = blockIdx.x * 32;
    int b  = n0 >> 13;                  // / Sz
    __shared__ float kvs[2][64][64];
    __shared__ float zs [2][64];
    __shared__ float pqs[32][64];
    __shared__ float dens[32];
    int tid = threadIdx.x;
    for (int i = tid; i < 2*64*64; i += 256)
        ((float*)kvs)[i] = d_kv[(size_t)b * (HKz*Mz*DHz) + i];
    for (int i = tid; i < 2*64; i += 256)
        ((float*)zs)[i] = d_z[b * (HKz*Mz) + i];

    for (int h = 0; h < Hz; h++) {
        int hk = h >> 2;
        for (int i = tid; i < 32*64; i += 256) {
            int r = i >> 6, m = i & 63;
            pqs[r][m] = d_pq[(size_t)(n0 + r) * (Hz*Mz) + h*Mz + m];
        }
        __syncthreads();
        if (tid < 32) {
            float s = 0.f;
            #pragma unroll 8
            for (int m = 0; m < 64; m++) s += pqs[tid][m] * zs[hk][m];
            dens[tid] = s + 1e-6f;
        }
        __syncthreads();
        int r = tid >> 3, d0 = (tid & 7) * 8;
        float acc[8];
        #pragma unroll
        for (int j = 0; j < 8; j++) acc[j] = 0.f;
        #pragma unroll 8
        for (int m = 0; m < 64; m++) {
            float p = pqs[r][m];
            float4 k0 = *(float4*)&kvs[hk][m][d0];
            float4 k1 = *(float4*)&kvs[hk][m][d0 + 4];
            acc[0] += p*k0.x; acc[1] += p*k0.y; acc[2] += p*k0.z; acc[3] += p*k0.w;
            acc[4] += p*k1.x; acc[5] += p*k1.y; acc[6] += p*k1.z; acc[7] += p*k1.w;
        }
        float inv = 1.f / dens[r];
        size_t base = (size_t)(n0 + r) * (Hz*DHz) + h*DHz + d0;
        #pragma unroll
        for (int j = 0; j < 8; j++) d_q[base + j] = to_tf32(acc[j] * inv);
        __syncthreads();
    }
}

// ---------------------------------------------------------------------------
// Mean pool partials
// ---------------------------------------------------------------------------
__global__ void pool_kernel() {
    int b = blockIdx.x;
    int d = blockIdx.y * 256 + threadIdx.x;
    size_t base = ((size_t)b * Sz + blockIdx.z * 512) * Dz + d;
    float s = 0.f;
    #pragma unroll 4
    for (int i = 0; i < 512; i++) s += d_x[base + (size_t)i * Dz];
    atomicAdd(&d_pool[b * Dz + d], s);
}

// ---------------------------------------------------------------------------
// Head
// ---------------------------------------------------------------------------
__global__ void head_kernel(const float* __restrict__ Wc,
                            const float* __restrict__ bc,
                            float* __restrict__ out) {
    int w = threadIdx.x >> 5, lane = threadIdx.x & 31;
    int b = w >> 1, c = w & 1;
    float s = 0.f;
    for (int d = lane; d < Dz; d += 32)
        s += d_pool[b * Dz + d] * Wc[d * NCLSz + c];
    #pragma unroll
    for (int o = 16; o; o >>= 1) s += __shfl_xor_sync(0xffffffffu, s, o);
    if (lane == 0) out[b * NCLSz + c] = s / (float)Sz + bc[c];
}

// ---------------------------------------------------------------------------
// Launch (graph-capturable: kernel launches only)
// ---------------------------------------------------------------------------
extern "C" void kernel_launch(void* const* d_in, const int* in_sizes, int n_in,
                              void* d_out, int out_size) {
    const int*   ids  = (const int*)  d_in[0];
    const float* emb  = (const float*)d_in[1];
    const float* Wq   = (const float*)d_in[2];
    const float* Wk   = (const float*)d_in[3];
    const float* Wv   = (const float*)d_in[4];
    const float* Wphi = (const float*)d_in[5];
    const float* Wo   = (const float*)d_in[6];
    const float* g1   = (const float*)d_in[7];
    const float* g2   = (const float*)d_in[8];
    const float* Wg   = (const float*)d_in[9];
    const float* Wu   = (const float*)d_in[10];
    const float* Wd   = (const float*)d_in[11];
    const float* Wc   = (const float*)d_in[12];
    const float* bc   = (const float*)d_in[13];
    float* out = (float*)d_out;

    float *px, *ph, *pq_, *pk_, *pv_, *ppq, *ppk, *pt1, *pwt;
    cudaGetSymbolAddress((void**)&px,  d_x);
    cudaGetSymbolAddress((void**)&ph,  d_h);
    cudaGetSymbolAddress((void**)&pq_, d_q);
    cudaGetSymbolAddress((void**)&pk_, d_k);
    cudaGetSymbolAddress((void**)&pv_, d_v);
    cudaGetSymbolAddress((void**)&ppq, d_pq);
    cudaGetSymbolAddress((void**)&ppk, d_pk);
    cudaGetSymbolAddress((void**)&pt1, d_t1);
    cudaGetSymbolAddress((void**)&pwt, d_wt);

    float* rWq = pwt;
    float* rWk = pwt + 262144;
    float* rWv = pwt + 327680;
    float* rWo = pwt + 393216;
    float* rWg = pwt + 655360;
    float* rWu = pwt + 1703936;
    float* rWd = pwt + 2752512;

    const int SMEM_T = (NSTG * ASTGf + NSTG * BSTGf) * 4;   // 87552 B
    cudaFuncSetAttribute(tgemm2_kernel<0>, cudaFuncAttributeMaxDynamicSharedMemorySize, SMEM_T);
    cudaFuncSetAttribute(tgemm2_kernel<1>, cudaFuncAttributeMaxDynamicSharedMemorySize, SMEM_T);
    cudaFuncSetAttribute(tgemm2_kernel<2>, cudaFuncAttributeMaxDynamicSharedMemorySize, SMEM_T);
    cudaFuncSetAttribute(tgemm2_kernel<3>, cudaFuncAttributeMaxDynamicSharedMemorySize, SMEM_T);

    // 0. tf32-round weights (layout preserved)
    round_copy_kernel<<<256,  256>>>(Wq, rWq, 65536);
    round_copy_kernel<<<64,   256>>>(Wk, rWk, 16384);
    round_copy_kernel<<<64,   256>>>(Wv, rWv, 16384);
    round_copy_kernel<<<256,  256>>>(Wo, rWo, 65536);
    round_copy_kernel<<<1024, 256>>>(Wg, rWg, 262144);
    round_copy_kernel<<<1024, 256>>>(Wu, rWu, 262144);
    round_copy_kernel<<<1024, 256>>>(Wd, rWd, 262144);

    // 1. zero accumulators
    zero_scratch_kernel<<<(Bz*HKz*Mz*DHz + 255)/256, 256>>>();
    // 2. embed + rmsnorm (h tf32)
    embed_rms_kernel<<<Nz, 128>>>(ids, emb, g1);
    // 3-5. QKV projections
    tgemm2_kernel<0><<<dim3(Dz/128,  Nz/256), 256, SMEM_T>>>(ph, rWq, pq_, Dz, Dz);
    tgemm2_kernel<0><<<dim3(1,       Nz/256), 256, SMEM_T>>>(ph, rWk, pk_, Dz, HKz*DHz);
    tgemm2_kernel<0><<<dim3(1,       Nz/256), 256, SMEM_T>>>(ph, rWv, pv_, Dz, HKz*DHz);
    // 6-7. Laplacian feature maps
    phi_kernel<<<dim3(Nz/64, Hz),  256>>>(pq_, Wphi, ppq, Hz*Mz);
    phi_kernel<<<dim3(Nz/64, HKz), 256>>>(pk_, Wphi, ppk, HKz*Mz);
    // 8. global state
    kv_reduce_kernel<<<dim3(Bz*HKz, 16), 256>>>();
    // 9. attention readout (into d_q, tf32)
    attn_kernel<<<Nz/32, 256>>>();
    // 10. x += attn @ Wo
    tgemm2_kernel<1><<<dim3(Dz/128, Nz/256), 256, SMEM_T>>>(pq_, rWo, px, Dz, Dz);
    // 11. h2 = rmsnorm(x, g2) (tf32)
    rms_kernel<<<Nz, 128>>>(g2);
    // 12. t1 = silu(h2 @ Wg)
    tgemm2_kernel<2><<<dim3(DFFz/128, Nz/256), 256, SMEM_T>>>(ph, rWg, pt1, Dz, DFFz);
    // 13. t1 = tf32(t1 * (h2 @ Wu))
    tgemm2_kernel<3><<<dim3(DFFz/128, Nz/256), 256, SMEM_T>>>(ph, rWu, pt1, Dz, DFFz);
    // 14. x += t1 @ Wd
    tgemm2_kernel<1><<<dim3(Dz/128, Nz/256), 256, SMEM_T>>>(pt1, rWd, px, DFFz, Dz);
    // 15. mean pool
    pool_kernel<<<dim3(Bz, Dz/256, Sz/512), 256>>>();
    // 16. head
    head_kernel<<<1, 512>>>(Wc, bc, out);
}

// round 9
// speedup vs baseline: 3.0035x; 1.3836x over previous
#include <cuda_runtime.h>
#include <cuda_fp16.h>
#include <math.h>
#include <stdint.h>

// ---------------------------------------------------------------------------
// Problem constants
// ---------------------------------------------------------------------------
#define Bz    8
#define Sz    8192
#define Nz    (Bz*Sz)          // 65536 tokens
#define Dz    512
#define Hz    8
#define HKz   2
#define DHz   64
#define Mz    64
#define DFFz  2048
#define NCLSz 2

// ---------------------------------------------------------------------------
// Scratch (device globals; no allocations allowed)
// ---------------------------------------------------------------------------
__device__ float  d_x [Nz*Dz];                       // residual stream (fp32)
__device__ __align__(16) __half d_h [Nz*Dz];         // rmsnorm out (fp16)
__device__ __align__(16) __half d_q [Nz*Dz];         // q, then attn out (fp16)
__device__ __align__(16) __half d_k [Nz*HKz*DHz];
__device__ __align__(16) __half d_v [Nz*HKz*DHz];
__device__ float  d_pq[Nz*Hz*Mz];
__device__ float  d_pk[Nz*HKz*Mz];
__device__ __align__(16) __half d_t1[(size_t)Nz*DFFz]; // FFN intermediate
__device__ float  d_kv[Bz*HKz*Mz*DHz];
__device__ float  d_z [Bz*HKz*Mz];
__device__ float  d_pool[Bz*Dz];
// fp16 transposed weights [N,K], packed:
// Wq@0(262144) Wk@262144(65536) Wv@327680(65536) Wo@393216(262144)
// Wg@655360(1048576) Wu@1703936(1048576) Wd@2752512(1048576)
__device__ __align__(16) __half d_wt[3801088];

// ---------------------------------------------------------------------------
// helpers
// ---------------------------------------------------------------------------
__device__ __forceinline__ uint32_t smem_u32(const void* p) {
    uint32_t a;
    asm("{ .reg .u64 t; cvta.to.shared.u64 t, %1; cvt.u32.u64 %0, t; }"
        : "=r"(a) : "l"(p));
    return a;
}
__device__ __forceinline__ void cp16(uint32_t s, const void* g) {
    asm volatile("cp.async.cg.shared.global [%0], [%1], 16;" :: "r"(s), "l"(g));
}
#define CP_COMMIT() asm volatile("cp.async.commit_group;" ::: "memory")

// ---------------------------------------------------------------------------
__global__ void zero_scratch_kernel() {
    int i = blockIdx.x * 256 + threadIdx.x;
    if (i < Bz*HKz*Mz*DHz) d_kv[i]   = 0.f;
    if (i < Bz*HKz*Mz)     d_z[i]    = 0.f;
    if (i < Bz*Dz)         d_pool[i] = 0.f;
}

// ---------------------------------------------------------------------------
// Weight transpose+convert: W [K,N] fp32 -> Wt [N,K] fp16
// grid (N/32, K/32), block (32,8)
// ---------------------------------------------------------------------------
__global__ void transpose_h_kernel(const float* __restrict__ W,
                                   __half* __restrict__ Wt, int K, int N) {
    __shared__ float t[32][33];
    int n0 = blockIdx.x * 32, k0 = blockIdx.y * 32;
    int tx = threadIdx.x, ty = threadIdx.y;
    #pragma unroll
    for (int i = 0; i < 32; i += 8)
        t[ty + i][tx] = W[(size_t)(k0 + ty + i) * N + n0 + tx];
    __syncthreads();
    #pragma unroll
    for (int i = 0; i < 32; i += 8)
        Wt[(size_t)(n0 + ty + i) * K + k0 + tx] = __float2half(t[tx][ty + i]);
}

// ---------------------------------------------------------------------------
// Embedding gather + RMSNorm (x fp32, h fp16)
// ---------------------------------------------------------------------------
__global__ void embed_rms_kernel(const int* __restrict__ ids,
                                 const float* __restrict__ emb,
                                 const float* __restrict__ g) {
    int n   = blockIdx.x;
    int tid = threadIdx.x;
    int id  = ids[n];
    float4 v = *(const float4*)&emb[(size_t)id * Dz + tid * 4];
    float ss = v.x*v.x + v.y*v.y + v.z*v.z + v.w*v.w;
    __shared__ float red[4];
    #pragma unroll
    for (int o = 16; o; o >>= 1) ss += __shfl_xor_sync(0xffffffffu, ss, o);
    if ((tid & 31) == 0) red[tid >> 5] = ss;
    __syncthreads();
    float tot = red[0] + red[1] + red[2] + red[3];
    float scale = rsqrtf(tot / (float)Dz + 1e-6f);
    *(float4*)&d_x[(size_t)n * Dz + tid * 4] = v;
    float4 gv = *(const float4*)&g[tid * 4];
    __half2 h0 = __floats2half2_rn(v.x*scale*gv.x, v.y*scale*gv.y);
    __half2 h1 = __floats2half2_rn(v.z*scale*gv.z, v.w*scale*gv.w);
    *(__half2*)&d_h[(size_t)n * Dz + tid * 4]     = h0;
    *(__half2*)&d_h[(size_t)n * Dz + tid * 4 + 2] = h1;
}

// RMSNorm of d_x into d_h (fp16)
__global__ void rms_kernel(const float* __restrict__ g) {
    int n   = blockIdx.x;
    int tid = threadIdx.x;
    float4 v = *(const float4*)&d_x[(size_t)n * Dz + tid * 4];
    float ss = v.x*v.x + v.y*v.y + v.z*v.z + v.w*v.w;
    __shared__ float red[4];
    #pragma unroll
    for (int o = 16; o; o >>= 1) ss += __shfl_xor_sync(0xffffffffu, ss, o);
    if ((tid & 31) == 0) red[tid >> 5] = ss;
    __syncthreads();
    float tot = red[0] + red[1] + red[2] + red[3];
    float scale = rsqrtf(tot / (float)Dz + 1e-6f);
    float4 gv = *(const float4*)&g[tid * 4];
    __half2 h0 = __floats2half2_rn(v.x*scale*gv.x, v.y*scale*gv.y);
    __half2 h1 = __floats2half2_rn(v.z*scale*gv.z, v.w*scale*gv.w);
    *(__half2*)&d_h[(size_t)n * Dz + tid * 4]     = h0;
    *(__half2*)&d_h[(size_t)n * Dz + tid * 4 + 2] = h1;
}

// ---------------------------------------------------------------------------
// FP16 mma.sync GEMM: block tile 256x128, warp tile 64x64 (8 warps 4x2),
// BK=32, 3-stage cp.async pipeline, m16n8k16 fp16 -> fp32 accum.
// A [Mr,K] fp16 row-major, Bt [Nc,K] fp16 row-major (pre-transposed).
// MODE 0: Chalf = acc; 1: Cfloat += acc; 2: Chalf = silu(acc);
// 3: Chalf = half(half2float(Chalf) * acc).
// grid (Nc/128, Mr/256), block 256, dynamic smem 92160 B.
// ---------------------------------------------------------------------------
#define AKP 40               // halves per A smem row (32 k + 8 pad = 80 B)
#define BKP 40               // halves per B smem row
#define ASTGh (256*AKP)      // 10240 halves / stage
#define BSTGh (128*BKP)      // 5120 halves / stage
#define NSTG  3

template<int MODE>
__global__ void __launch_bounds__(256)
hgemm_kernel(const __half* __restrict__ A, const __half* __restrict__ Bt,
             void* __restrict__ Cv, int K, int Nc) {
    extern __shared__ __half hsm[];
    __half* As = hsm;                      // [3][256][AKP]
    __half* Bs = hsm + NSTG * ASTGh;       // [3][128][BKP]
    uint32_t uA = smem_u32(As);
    uint32_t uB = smem_u32(Bs);

    int tid  = threadIdx.x;
    int lane = tid & 31;
    int warp = tid >> 5;
    int wm  = (warp >> 1) * 64;            // 0,64,128,192
    int wn  = (warp & 1) * 64;             // 0,64
    int gid = lane >> 2;                   // 0..7
    int tig = lane & 3;                    // 0..3

    const __half* Ablk = A  + (size_t)(blockIdx.y * 256) * K;
    const __half* Bblk = Bt + (size_t)(blockIdx.x * 128) * K;

    float acc[4][8][4];
    #pragma unroll
    for (int i = 0; i < 4; i++)
        #pragma unroll
        for (int j = 0; j < 8; j++)
            #pragma unroll
            for (int r = 0; r < 4; r++) acc[i][j][r] = 0.f;

    int cr = tid >> 2;                     // 0..63 copy row
    int cc = tid & 3;                      // 0..3 chunk (8 halves)

    int NS = K >> 5;                       // K/32 stages

    auto load_stage = [&](int s, int buf) {
        int k0 = s << 5;
        uint32_t ab = uA + (uint32_t)buf * (ASTGh * 2);
        uint32_t bb = uB + (uint32_t)buf * (BSTGh * 2);
        #pragma unroll
        for (int t = 0; t < 4; t++) {      // A: 256 rows
            int m = cr + t * 64;
            cp16(ab + (uint32_t)(m * (AKP*2) + cc * 16),
                 Ablk + (size_t)m * K + k0 + cc * 8);
        }
        #pragma unroll
        for (int t = 0; t < 2; t++) {      // B: 128 rows
            int n = cr + t * 64;
            cp16(bb + (uint32_t)(n * (BKP*2) + cc * 16),
                 Bblk + (size_t)n * K + k0 + cc * 8);
        }
        CP_COMMIT();
    };

    load_stage(0, 0);
    load_stage(1, 1);

    int bufC = 0, bufL = 2;
    for (int s = 0; s < NS; s++) {
        if (s + 2 < NS) load_stage(s + 2, bufL);
        if (s + 2 < NS)      asm volatile("cp.async.wait_group 2;" ::: "memory");
        else if (s + 1 < NS) asm volatile("cp.async.wait_group 1;" ::: "memory");
        else                 asm volatile("cp.async.wait_group 0;" ::: "memory");
        __syncthreads();

        const __half* Ab = As + bufC * ASTGh;
        const __half* Bb = Bs + bufC * BSTGh;
        #pragma unroll
        for (int kk = 0; kk < 32; kk += 16) {
            uint32_t a[4][4];
            #pragma unroll
            for (int mt = 0; mt < 4; mt++) {
                int r0 = wm + mt * 16 + gid;
                a[mt][0] = *(const uint32_t*)&Ab[r0 * AKP + kk + 2*tig];
                a[mt][1] = *(const uint32_t*)&Ab[(r0 + 8) * AKP + kk + 2*tig];
                a[mt][2] = *(const uint32_t*)&Ab[r0 * AKP + kk + 2*tig + 8];
                a[mt][3] = *(const uint32_t*)&Ab[(r0 + 8) * AKP + kk + 2*tig + 8];
            }
            uint32_t b[8][2];
            #pragma unroll
            for (int nt = 0; nt < 8; nt++) {
                int n = wn + nt * 8 + gid;
                b[nt][0] = *(const uint32_t*)&Bb[n * BKP + kk + 2*tig];
                b[nt][1] = *(const uint32_t*)&Bb[n * BKP + kk + 2*tig + 8];
            }
            #pragma unroll
            for (int mt = 0; mt < 4; mt++)
                #pragma unroll
                for (int nt = 0; nt < 8; nt++) {
                    asm volatile(
                        "mma.sync.aligned.m16n8k16.row.col.f32.f16.f16.f32 "
                        "{%0,%1,%2,%3}, {%4,%5,%6,%7}, {%8,%9}, {%0,%1,%2,%3};"
                        : "+f"(acc[mt][nt][0]), "+f"(acc[mt][nt][1]),
                          "+f"(acc[mt][nt][2]), "+f"(acc[mt][nt][3])
                        : "r"(a[mt][0]), "r"(a[mt][1]), "r"(a[mt][2]), "r"(a[mt][3]),
                          "r"(b[nt][0]), "r"(b[nt][1]));
                }
        }
        __syncthreads();
        bufC++; if (bufC == NSTG) bufC = 0;
        bufL++; if (bufL == NSTG) bufL = 0;
    }

    // epilogue: c0,c1 = row gid cols 2tig,2tig+1; c2,c3 = row gid+8
    int rowBase = blockIdx.y * 256 + wm;
    int colBase = blockIdx.x * 128 + wn;
    #pragma unroll
    for (int mt = 0; mt < 4; mt++) {
        #pragma unroll
        for (int nt = 0; nt < 8; nt++) {
            #pragma unroll
            for (int half_ = 0; half_ < 2; half_++) {
                int row = rowBase + mt * 16 + gid + half_ * 8;
                int col = colBase + nt * 8 + tig * 2;
                size_t off = (size_t)row * Nc + col;
                float v0 = acc[mt][nt][half_ * 2 + 0];
                float v1 = acc[mt][nt][half_ * 2 + 1];
                if (MODE == 0) {
                    *(__half2*)((__half*)Cv + off) = __floats2half2_rn(v0, v1);
                } else if (MODE == 1) {
                    float* C = (float*)Cv;
                    float2 c = *(float2*)&C[off];
                    c.x += v0; c.y += v1;
                    *(float2*)&C[off] = c;
                } else if (MODE == 2) {
                    v0 = v0 / (1.f + expf(-v0));
                    v1 = v1 / (1.f + expf(-v1));
                    *(__half2*)((__half*)Cv + off) = __floats2half2_rn(v0, v1);
                } else {
                    __half2 c = *(__half2*)((__half*)Cv + off);
                    float2 cf = __half22float2(c);
                    *(__half2*)((__half*)Cv + off) =
                        __floats2half2_rn(v0 * cf.x, v1 * cf.y);
                }
            }
        }
    }
}

// ---------------------------------------------------------------------------
// phi projection: out[n, h*64+m] = exp(-|sum_d in[n, h*64+d]*Wphi[d,m]|)
// in is fp16, out fp32. grid (Nz/64, heads), block 256
// ---------------------------------------------------------------------------
__global__ void phi_kernel(const __half* __restrict__ in,
                           const float* __restrict__ Wphi,
                           float* __restrict__ out, int ld) {
    int h  = blockIdx.y;
    int n0 = blockIdx.x * 64;
    __shared__ float Ws[64][65];
    __shared__ float Qs[64][65];
    int tid = threadIdx.x;
    for (int i = tid; i < 4096; i += 256) {
        int r = i >> 6, c = i & 63;
        Ws[r][c] = Wphi[i];
        Qs[r][c] = __half2float(in[(size_t)(n0 + r) * ld + h * 64 + c]);
    }
    __syncthreads();
    int r  = tid >> 2;
    int m0 = (tid & 3) * 16;
    float acc[16];
    #pragma unroll
    for (int j = 0; j < 16; j++) acc[j] = 0.f;
    #pragma unroll 8
    for (int d = 0; d < 64; d++) {
        float qv = Qs[r][d];
        #pragma unroll
        for (int j = 0; j < 16; j++) acc[j] += qv * Ws[d][m0 + j];
    }
    size_t base = (size_t)(n0 + r) * ld + h * 64 + m0;
    #pragma unroll
    for (int j = 0; j < 16; j++)
        out[base + j] = expf(-fabsf(acc[j]));
}

// ---------------------------------------------------------------------------
// kv state reduction: kv[b,hk,m,d] = sum_s pk * v;  z[b,hk,m] = sum_s pk
// ---------------------------------------------------------------------------
__global__ void kv_reduce_kernel() {
    int bh = blockIdx.x;             // 0..15
    int b  = bh >> 1, hk = bh & 1;
    int s0 = blockIdx.y * 512;
    __shared__ float pks[8][64];
    __shared__ float vs [8][64];
    int tid = threadIdx.x;
    int m  = tid >> 2;
    int d0 = (tid & 3) * 16;
    float acc[16];
    #pragma unroll
    for (int j = 0; j < 16; j++) acc[j] = 0.f;
    float zacc = 0.f;
    int rr = tid >> 6;               // 0..3
    int cc = tid & 63;
    for (int ss = 0; ss < 512; ss += 8) {
        size_t n = (size_t)b * Sz + s0 + ss;
        pks[rr  ][cc] = d_pk[(n + rr    ) * (HKz*Mz) + hk*Mz + cc];
        pks[rr+4][cc] = d_pk[(n + rr + 4) * (HKz*Mz) + hk*Mz + cc];
        vs [rr  ][cc] = __half2float(d_v[(n + rr    ) * (HKz*DHz) + hk*DHz + cc]);
        vs [rr+4][cc] = __half2float(d_v[(n + rr + 4) * (HKz*DHz) + hk*DHz + cc]);
        __syncthreads();
        #pragma unroll
        for (int t = 0; t < 8; t++) {
            float pm = pks[t][m];
            zacc += pm;
            #pragma unroll
            for (int j = 0; j < 16; j++) acc[j] += pm * vs[t][d0 + j];
        }
        __syncthreads();
    }
    size_t base = ((size_t)bh * Mz + m) * DHz + d0;
    #pragma unroll
    for (int j = 0; j < 16; j++) atomicAdd(&d_kv[base + j], acc[j]);
    if ((tid & 3) == 0) atomicAdd(&d_z[bh * Mz + m], zacc);
}

// ---------------------------------------------------------------------------
// Attention readout: attn[n, h*64+d] = (pq . kv)/(pq . z + eps) -> d_q (fp16)
// ---------------------------------------------------------------------------
__global__ void attn_kernel() {
    int n0 = blockIdx.x * 32;
    int b  = n0 >> 13;                  // / Sz
    __shared__ float kvs[2][64][64];
    __shared__ float zs [2][64];
    __shared__ float pqs[32][64];
    __shared__ float dens[32];
    int tid = threadIdx.x;
    for (int i = tid; i < 2*64*64; i += 256)
        ((float*)kvs)[i] = d_kv[(size_t)b * (HKz*Mz*DHz) + i];
    for (int i = tid; i < 2*64; i += 256)
        ((float*)zs)[i] = d_z[b * (HKz*Mz) + i];

    for (int h = 0; h < Hz; h++) {
        int hk = h >> 2;
        for (int i = tid; i < 32*64; i += 256) {
            int r = i >> 6, m = i & 63;
            pqs[r][m] = d_pq[(size_t)(n0 + r) * (Hz*Mz) + h*Mz + m];
        }
        __syncthreads();
        if (tid < 32) {
            float s = 0.f;
            #pragma unroll 8
            for (int m = 0; m < 64; m++) s += pqs[tid][m] * zs[hk][m];
            dens[tid] = s + 1e-6f;
        }
        __syncthreads();
        int r = tid >> 3, d0 = (tid & 7) * 8;
        float acc[8];
        #pragma unroll
        for (int j = 0; j < 8; j++) acc[j] = 0.f;
        #pragma unroll 8
        for (int m = 0; m < 64; m++) {
            float p = pqs[r][m];
            float4 k0 = *(float4*)&kvs[hk][m][d0];
            float4 k1 = *(float4*)&kvs[hk][m][d0 + 4];
            acc[0] += p*k0.x; acc[1] += p*k0.y; acc[2] += p*k0.z; acc[3] += p*k0.w;
            acc[4] += p*k1.x; acc[5] += p*k1.y; acc[6] += p*k1.z; acc[7] += p*k1.w;
        }
        float inv = 1.f / dens[r];
        size_t base = (size_t)(n0 + r) * (Hz*DHz) + h*DHz + d0;
        #pragma unroll
        for (int j = 0; j < 8; j++)
            d_q[base + j] = __float2half(acc[j] * inv);
        __syncthreads();
    }
}

// ---------------------------------------------------------------------------
// Mean pool partials
// ---------------------------------------------------------------------------
__global__ void pool_kernel() {
    int b = blockIdx.x;
    int d = blockIdx.y * 256 + threadIdx.x;
    size_t base = ((size_t)b * Sz + blockIdx.z * 512) * Dz + d;
    float s = 0.f;
    #pragma unroll 4
    for (int i = 0; i < 512; i++) s += d_x[base + (size_t)i * Dz];
    atomicAdd(&d_pool[b * Dz + d], s);
}

// ---------------------------------------------------------------------------
// Head
// ---------------------------------------------------------------------------
__global__ void head_kernel(const float* __restrict__ Wc,
                            const float* __restrict__ bc,
                            float* __restrict__ out) {
    int w = threadIdx.x >> 5, lane = threadIdx.x & 31;
    int b = w >> 1, c = w & 1;
    float s = 0.f;
    for (int d = lane; d < Dz; d += 32)
        s += d_pool[b * Dz + d] * Wc[d * NCLSz + c];
    #pragma unroll
    for (int o = 16; o; o >>= 1) s += __shfl_xor_sync(0xffffffffu, s, o);
    if (lane == 0) out[b * NCLSz + c] = s / (float)Sz + bc[c];
}

// ---------------------------------------------------------------------------
// Launch (graph-capturable: kernel launches only)
// ---------------------------------------------------------------------------
extern "C" void kernel_launch(void* const* d_in, const int* in_sizes, int n_in,
                              void* d_out, int out_size) {
    const int*   ids  = (const int*)  d_in[0];
    const float* emb  = (const float*)d_in[1];
    const float* Wq   = (const float*)d_in[2];
    const float* Wk   = (const float*)d_in[3];
    const float* Wv   = (const float*)d_in[4];
    const float* Wphi = (const float*)d_in[5];
    const float* Wo   = (const float*)d_in[6];
    const float* g1   = (const float*)d_in[7];
    const float* g2   = (const float*)d_in[8];
    const float* Wg   = (const float*)d_in[9];
    const float* Wu   = (const float*)d_in[10];
    const float* Wd   = (const float*)d_in[11];
    const float* Wc   = (const float*)d_in[12];
    const float* bc   = (const float*)d_in[13];
    float* out = (float*)d_out;

    float *px, *ppq, *ppk;
    __half *ph, *pq_, *pk_, *pv_, *pt1, *pwt;
    cudaGetSymbolAddress((void**)&px,  d_x);
    cudaGetSymbolAddress((void**)&ph,  d_h);
    cudaGetSymbolAddress((void**)&pq_, d_q);
    cudaGetSymbolAddress((void**)&pk_, d_k);
    cudaGetSymbolAddress((void**)&pv_, d_v);
    cudaGetSymbolAddress((void**)&ppq, d_pq);
    cudaGetSymbolAddress((void**)&ppk, d_pk);
    cudaGetSymbolAddress((void**)&pt1, d_t1);
    cudaGetSymbolAddress((void**)&pwt, d_wt);

    __half* tWq = pwt;
    __half* tWk = pwt + 262144;
    __half* tWv = pwt + 327680;
    __half* tWo = pwt + 393216;
    __half* tWg = pwt + 655360;
    __half* tWu = pwt + 1703936;
    __half* tWd = pwt + 2752512;

    const int SMEM_H = (NSTG * ASTGh + NSTG * BSTGh) * 2;   // 92160 B
    cudaFuncSetAttribute(hgemm_kernel<0>, cudaFuncAttributeMaxDynamicSharedMemorySize, SMEM_H);
    cudaFuncSetAttribute(hgemm_kernel<1>, cudaFuncAttributeMaxDynamicSharedMemorySize, SMEM_H);
    cudaFuncSetAttribute(hgemm_kernel<2>, cudaFuncAttributeMaxDynamicSharedMemorySize, SMEM_H);
    cudaFuncSetAttribute(hgemm_kernel<3>, cudaFuncAttributeMaxDynamicSharedMemorySize, SMEM_H);

    // 0. transpose+convert weights to fp16 [N,K]
    transpose_h_kernel<<<dim3(Dz/32,   Dz/32),   dim3(32,8)>>>(Wq, tWq, Dz,   Dz);
    transpose_h_kernel<<<dim3(128/32,  Dz/32),   dim3(32,8)>>>(Wk, tWk, Dz,   128);
    transpose_h_kernel<<<dim3(128/32,  Dz/32),   dim3(32,8)>>>(Wv, tWv, Dz,   128);
    transpose_h_kernel<<<dim3(Dz/32,   Dz/32),   dim3(32,8)>>>(Wo, tWo, Dz,   Dz);
    transpose_h_kernel<<<dim3(DFFz/32, Dz/32),   dim3(32,8)>>>(Wg, tWg, Dz,   DFFz);
    transpose_h_kernel<<<dim3(DFFz/32, Dz/32),   dim3(32,8)>>>(Wu, tWu, Dz,   DFFz);
    transpose_h_kernel<<<dim3(Dz/32,   DFFz/32), dim3(32,8)>>>(Wd, tWd, DFFz, Dz);

    // 1. zero accumulators
    zero_scratch_kernel<<<(Bz*HKz*Mz*DHz + 255)/256, 256>>>();
    // 2. embed + rmsnorm (h fp16)
    embed_rms_kernel<<<Nz, 128>>>(ids, emb, g1);
    // 3-5. QKV projections (fp16 mma)
    hgemm_kernel<0><<<dim3(Dz/128,  Nz/256), 256, SMEM_H>>>(ph, tWq, pq_, Dz, Dz);
    hgemm_kernel<0><<<dim3(1,       Nz/256), 256, SMEM_H>>>(ph, tWk, pk_, Dz, HKz*DHz);
    hgemm_kernel<0><<<dim3(1,       Nz/256), 256, SMEM_H>>>(ph, tWv, pv_, Dz, HKz*DHz);
    // 6-7. Laplacian feature maps
    phi_kernel<<<dim3(Nz/64, Hz),  256>>>(pq_, Wphi, ppq, Hz*Mz);
    phi_kernel<<<dim3(Nz/64, HKz), 256>>>(pk_, Wphi, ppk, HKz*Mz);
    // 8. global state
    kv_reduce_kernel<<<dim3(Bz*HKz, 16), 256>>>();
    // 9. attention readout (into d_q, fp16)
    attn_kernel<<<Nz/32, 256>>>();
    // 10. x += attn @ Wo
    hgemm_kernel<1><<<dim3(Dz/128, Nz/256), 256, SMEM_H>>>(pq_, tWo, px, Dz, Dz);
    // 11. h2 = rmsnorm(x, g2) (fp16)
    rms_kernel<<<Nz, 128>>>(g2);
    // 12. t1 = silu(h2 @ Wg)  (fp16)
    hgemm_kernel<2><<<dim3(DFFz/128, Nz/256), 256, SMEM_H>>>(ph, tWg, pt1, Dz, DFFz);
    // 13. t1 = half(t1 * (h2 @ Wu))
    hgemm_kernel<3><<<dim3(DFFz/128, Nz/256), 256, SMEM_H>>>(ph, tWu, pt1, Dz, DFFz);
    // 14. x += t1 @ Wd
    hgemm_kernel<1><<<dim3(Dz/128, Nz/256), 256, SMEM_H>>>(pt1, tWd, px, DFFz, Dz);
    // 15. mean pool
    pool_kernel<<<dim3(Bz, Dz/256, Sz/512), 256>>>();
    // 16. head
    head_kernel<<<1, 512>>>(Wc, bc, out);
}

// round 10
// speedup vs baseline: 3.0240x; 1.0068x over previous
#include <cuda_runtime.h>
#include <cuda_fp16.h>
#include <math.h>
#include <stdint.h>

// ---------------------------------------------------------------------------
// Problem constants
// ---------------------------------------------------------------------------
#define Bz    8
#define Sz    8192
#define Nz    (Bz*Sz)          // 65536 tokens
#define Dz    512
#define Hz    8
#define HKz   2
#define DHz   64
#define Mz    64
#define DFFz  2048
#define NCLSz 2
#define QKVW  768              // fused QKV output width

// ---------------------------------------------------------------------------
// Scratch (device globals; no allocations allowed)
// ---------------------------------------------------------------------------
__device__ float  d_x [Nz*Dz];                          // residual (fp32)
__device__ __align__(16) __half d_h [Nz*Dz];            // rmsnorm out (fp16)
__device__ __align__(16) __half d_q [Nz*Dz];            // attn out (fp16)
__device__ __align__(16) __half d_qkv[(size_t)Nz*QKVW]; // fused q|k|v (fp16)
__device__ float  d_pq[Nz*Hz*Mz];
__device__ float  d_pk[Nz*HKz*Mz];
__device__ __align__(16) __half d_t1[(size_t)Nz*DFFz];  // FFN intermediate
__device__ float  d_kv[Bz*HKz*Mz*DHz];
__device__ float  d_z [Bz*HKz*Mz];
__device__ float  d_pool[Bz*Dz];
// fp16 transposed weights [N,K] packed. Rows of the fused QKV matrix [768,512]:
// Wq^T rows 0-511 @0, Wk^T rows 512-639 @262144, Wv^T rows 640-767 @327680.
// Then Wo@393216(262144) Wg@655360(1048576) Wu@1703936(1048576) Wd@2752512(1048576)
__device__ __align__(16) __half d_wt[3801088];

// ---------------------------------------------------------------------------
// helpers
// ---------------------------------------------------------------------------
__device__ __forceinline__ uint32_t smem_u32(const void* p) {
    uint32_t a;
    asm("{ .reg .u64 t; cvta.to.shared.u64 t, %1; cvt.u32.u64 %0, t; }"
        : "=r"(a) : "l"(p));
    return a;
}
__device__ __forceinline__ void cp16(uint32_t s, const void* g) {
    asm volatile("cp.async.cg.shared.global [%0], [%1], 16;" :: "r"(s), "l"(g));
}
#define CP_COMMIT() asm volatile("cp.async.commit_group;" ::: "memory")
__device__ __forceinline__ void ldsm4(uint32_t& r0, uint32_t& r1,
                                      uint32_t& r2, uint32_t& r3, uint32_t addr) {
    asm volatile("ldmatrix.sync.aligned.m8n8.x4.shared.b16 {%0,%1,%2,%3}, [%4];"
                 : "=r"(r0), "=r"(r1), "=r"(r2), "=r"(r3) : "r"(addr));
}

// ---------------------------------------------------------------------------
__global__ void zero_scratch_kernel() {
    int i = blockIdx.x * 256 + threadIdx.x;
    if (i < Bz*HKz*Mz*DHz) d_kv[i]   = 0.f;
    if (i < Bz*HKz*Mz)     d_z[i]    = 0.f;
    if (i < Bz*Dz)         d_pool[i] = 0.f;
}

// ---------------------------------------------------------------------------
// Weight transpose+convert: W [K,N] fp32 -> Wt [N,K] fp16
// ---------------------------------------------------------------------------
__global__ void transpose_h_kernel(const float* __restrict__ W,
                                   __half* __restrict__ Wt, int K, int N) {
    __shared__ float t[32][33];
    int n0 = blockIdx.x * 32, k0 = blockIdx.y * 32;
    int tx = threadIdx.x, ty = threadIdx.y;
    #pragma unroll
    for (int i = 0; i < 32; i += 8)
        t[ty + i][tx] = W[(size_t)(k0 + ty + i) * N + n0 + tx];
    __syncthreads();
    #pragma unroll
    for (int i = 0; i < 32; i += 8)
        Wt[(size_t)(n0 + ty + i) * K + k0 + tx] = __float2half(t[tx][ty + i]);
}

// ---------------------------------------------------------------------------
// Embedding gather + RMSNorm (x fp32, h fp16)
// ---------------------------------------------------------------------------
__global__ void embed_rms_kernel(const int* __restrict__ ids,
                                 const float* __restrict__ emb,
                                 const float* __restrict__ g) {
    int n   = blockIdx.x;
    int tid = threadIdx.x;
    int id  = ids[n];
    float4 v = *(const float4*)&emb[(size_t)id * Dz + tid * 4];
    float ss = v.x*v.x + v.y*v.y + v.z*v.z + v.w*v.w;
    __shared__ float red[4];
    #pragma unroll
    for (int o = 16; o; o >>= 1) ss += __shfl_xor_sync(0xffffffffu, ss, o);
    if ((tid & 31) == 0) red[tid >> 5] = ss;
    __syncthreads();
    float tot = red[0] + red[1] + red[2] + red[3];
    float scale = rsqrtf(tot / (float)Dz + 1e-6f);
    *(float4*)&d_x[(size_t)n * Dz + tid * 4] = v;
    float4 gv = *(const float4*)&g[tid * 4];
    __half2 h0 = __floats2half2_rn(v.x*scale*gv.x, v.y*scale*gv.y);
    __half2 h1 = __floats2half2_rn(v.z*scale*gv.z, v.w*scale*gv.w);
    *(__half2*)&d_h[(size_t)n * Dz + tid * 4]     = h0;
    *(__half2*)&d_h[(size_t)n * Dz + tid * 4 + 2] = h1;
}

// RMSNorm of d_x into d_h (fp16)
__global__ void rms_kernel(const float* __restrict__ g) {
    int n   = blockIdx.x;
    int tid = threadIdx.x;
    float4 v = *(const float4*)&d_x[(size_t)n * Dz + tid * 4];
    float ss = v.x*v.x + v.y*v.y + v.z*v.z + v.w*v.w;
    __shared__ float red[4];
    #pragma unroll
    for (int o = 16; o; o >>= 1) ss += __shfl_xor_sync(0xffffffffu, ss, o);
    if ((tid & 31) == 0) red[tid >> 5] = ss;
    __syncthreads();
    float tot = red[0] + red[1] + red[2] + red[3];
    float scale = rsqrtf(tot / (float)Dz + 1e-6f);
    float4 gv = *(const float4*)&g[tid * 4];
    __half2 h0 = __floats2half2_rn(v.x*scale*gv.x, v.y*scale*gv.y);
    __half2 h1 = __floats2half2_rn(v.z*scale*gv.z, v.w*scale*gv.w);
    *(__half2*)&d_h[(size_t)n * Dz + tid * 4]     = h0;
    *(__half2*)&d_h[(size_t)n * Dz + tid * 4 + 2] = h1;
}

// ---------------------------------------------------------------------------
// FP16 mma.sync GEMM with ldmatrix fragment loads.
// Block tile 256x128, warp tile 64x64 (8 warps 4x2), BK=32, 3-stage cp.async.
// A [Mr,K] fp16 row-major, Bt [Nc,K] fp16 row-major.
// MODE 0: Chalf = acc; 1: Cfloat += acc; 2: Chalf = silu(acc);
// 3: Chalf = half(half2float(Chalf) * acc).
// grid (Nc/128, Mr/256), block 256, dynamic smem 92160 B.
// ---------------------------------------------------------------------------
#define AKP 40               // halves per A smem row (32 k + 8 pad = 80 B)
#define BKP 40               // halves per B smem row
#define ASTGh (256*AKP)      // 10240 halves / stage
#define BSTGh (128*BKP)      // 5120 halves / stage
#define NSTG  3

template<int MODE>
__global__ void __launch_bounds__(256)
hgemm_kernel(const __half* __restrict__ A, const __half* __restrict__ Bt,
             void* __restrict__ Cv, int K, int Nc) {
    extern __shared__ __half hsm[];
    __half* As = hsm;                      // [3][256][AKP]
    __half* Bs = hsm + NSTG * ASTGh;       // [3][128][BKP]
    uint32_t uA = smem_u32(As);
    uint32_t uB = smem_u32(Bs);

    int tid  = threadIdx.x;
    int lane = tid & 31;
    int warp = tid >> 5;
    int wm  = (warp >> 1) * 64;            // 0,64,128,192
    int wn  = (warp & 1) * 64;             // 0,64
    int gid = lane >> 2;                   // 0..7
    int tig = lane & 3;                    // 0..3

    // ldmatrix lane-address components
    int aRowL = (lane & 7) + ((lane >> 3) & 1) * 8;  // row within 16-row A tile
    int aColL = (lane >> 4) * 8;                     // k offset 0/8
    int jj    = lane >> 3;                           // B matrix index 0..3
    int bRowL = ((jj >> 1) * 8) + (lane & 7);        // row within 16-row B pair
    int bColL = (jj & 1) * 8;                        // k offset 0/8

    const __half* Ablk = A  + (size_t)(blockIdx.y * 256) * K;
    const __half* Bblk = Bt + (size_t)(blockIdx.x * 128) * K;

    float acc[4][8][4];
    #pragma unroll
    for (int i = 0; i < 4; i++)
        #pragma unroll
        for (int j = 0; j < 8; j++)
            #pragma unroll
            for (int r = 0; r < 4; r++) acc[i][j][r] = 0.f;

    int cr = tid >> 2;                     // 0..63 copy row
    int cc = tid & 3;                      // 0..3 chunk (8 halves)

    int NS = K >> 5;                       // K/32 stages

    auto load_stage = [&](int s, int buf) {
        int k0 = s << 5;
        uint32_t ab = uA + (uint32_t)buf * (ASTGh * 2);
        uint32_t bb = uB + (uint32_t)buf * (BSTGh * 2);
        #pragma unroll
        for (int t = 0; t < 4; t++) {      // A: 256 rows
            int m = cr + t * 64;
            cp16(ab + (uint32_t)(m * (AKP*2) + cc * 16),
                 Ablk + (size_t)m * K + k0 + cc * 8);
        }
        #pragma unroll
        for (int t = 0; t < 2; t++) {      // B: 128 rows
            int n = cr + t * 64;
            cp16(bb + (uint32_t)(n * (BKP*2) + cc * 16),
                 Bblk + (size_t)n * K + k0 + cc * 8);
        }
        CP_COMMIT();
    };

    load_stage(0, 0);
    load_stage(1, 1);

    int bufC = 0, bufL = 2;
    for (int s = 0; s < NS; s++) {
        if (s + 2 < NS) load_stage(s + 2, bufL);
        if (s + 2 < NS)      asm volatile("cp.async.wait_group 2;" ::: "memory");
        else if (s + 1 < NS) asm volatile("cp.async.wait_group 1;" ::: "memory");
        else                 asm volatile("cp.async.wait_group 0;" ::: "memory");
        __syncthreads();

        uint32_t aBase = uA + (uint32_t)bufC * (ASTGh * 2);
        uint32_t bBase = uB + (uint32_t)bufC * (BSTGh * 2);
        #pragma unroll
        for (int kk = 0; kk < 32; kk += 16) {
            uint32_t a[4][4];
            #pragma unroll
            for (int mt = 0; mt < 4; mt++) {
                uint32_t addr = aBase +
                    (uint32_t)((wm + mt * 16 + aRowL) * AKP + kk + aColL) * 2;
                ldsm4(a[mt][0], a[mt][1], a[mt][2], a[mt][3], addr);
            }
            uint32_t b[8][2];
            #pragma unroll
            for (int p = 0; p < 4; p++) {  // nt pair (2p, 2p+1)
                uint32_t addr = bBase +
                    (uint32_t)((wn + p * 16 + bRowL) * BKP + kk + bColL) * 2;
                ldsm4(b[2*p][0], b[2*p][1], b[2*p+1][0], b[2*p+1][1], addr);
            }
            #pragma unroll
            for (int mt = 0; mt < 4; mt++)
                #pragma unroll
                for (int nt = 0; nt < 8; nt++) {
                    asm volatile(
                        "mma.sync.aligned.m16n8k16.row.col.f32.f16.f16.f32 "
                        "{%0,%1,%2,%3}, {%4,%5,%6,%7}, {%8,%9}, {%0,%1,%2,%3};"
                        : "+f"(acc[mt][nt][0]), "+f"(acc[mt][nt][1]),
                          "+f"(acc[mt][nt][2]), "+f"(acc[mt][nt][3])
                        : "r"(a[mt][0]), "r"(a[mt][1]), "r"(a[mt][2]), "r"(a[mt][3]),
                          "r"(b[nt][0]), "r"(b[nt][1]));
                }
        }
        __syncthreads();
        bufC++; if (bufC == NSTG) bufC = 0;
        bufL++; if (bufL == NSTG) bufL = 0;
    }

    // epilogue: c0,c1 = row gid cols 2tig,2tig+1; c2,c3 = row gid+8
    int rowBase = blockIdx.y * 256 + wm;
    int colBase = blockIdx.x * 128 + wn;
    #pragma unroll
    for (int mt = 0; mt < 4; mt++) {
        #pragma unroll
        for (int nt = 0; nt < 8; nt++) {
            #pragma unroll
            for (int half_ = 0; half_ < 2; half_++) {
                int row = rowBase + mt * 16 + gid + half_ * 8;
                int col = colBase + nt * 8 + tig * 2;
                size_t off = (size_t)row * Nc + col;
                float v0 = acc[mt][nt][half_ * 2 + 0];
                float v1 = acc[mt][nt][half_ * 2 + 1];
                if (MODE == 0) {
                    *(__half2*)((__half*)Cv + off) = __floats2half2_rn(v0, v1);
                } else if (MODE == 1) {
                    float* C = (float*)Cv;
                    float2 c = *(float2*)&C[off];
                    c.x += v0; c.y += v1;
                    *(float2*)&C[off] = c;
                } else if (MODE == 2) {
                    v0 = v0 / (1.f + expf(-v0));
                    v1 = v1 / (1.f + expf(-v1));
                    *(__half2*)((__half*)Cv + off) = __floats2half2_rn(v0, v1);
                } else {
                    __half2 c = *(__half2*)((__half*)Cv + off);
                    float2 cf = __half22float2(c);
                    *(__half2*)((__half*)Cv + off) =
                        __floats2half2_rn(v0 * cf.x, v1 * cf.y);
                }
            }
        }
    }
}

// ---------------------------------------------------------------------------
// phi projection: out[n, h*64+m] = exp(-|sum_d in[n*ldin + h*64+d]*Wphi[d,m]|)
// in fp16 (stride ldin), out fp32 (stride ldout).
// ---------------------------------------------------------------------------
__global__ void phi_kernel(const __half* __restrict__ in,
                           const float* __restrict__ Wphi,
                           float* __restrict__ out, int ldin, int ldout) {
    int h  = blockIdx.y;
    int n0 = blockIdx.x * 64;
    __shared__ float Ws[64][65];
    __shared__ float Qs[64][65];
    int tid = threadIdx.x;
    for (int i = tid; i < 4096; i += 256) {
        int r = i >> 6, c = i & 63;
        Ws[r][c] = Wphi[i];
        Qs[r][c] = __half2float(in[(size_t)(n0 + r) * ldin + h * 64 + c]);
    }
    __syncthreads();
    int r  = tid >> 2;
    int m0 = (tid & 3) * 16;
    float acc[16];
    #pragma unroll
    for (int j = 0; j < 16; j++) acc[j] = 0.f;
    #pragma unroll 8
    for (int d = 0; d < 64; d++) {
        float qv = Qs[r][d];
        #pragma unroll
        for (int j = 0; j < 16; j++) acc[j] += qv * Ws[d][m0 + j];
    }
    size_t base = (size_t)(n0 + r) * ldout + h * 64 + m0;
    #pragma unroll
    for (int j = 0; j < 16; j++)
        out[base + j] = expf(-fabsf(acc[j]));
}

// ---------------------------------------------------------------------------
// kv state reduction: kv[b,hk,m,d] = sum_s pk * v;  z[b,hk,m] = sum_s pk
// v read from fused qkv buffer at column 640 + hk*64, row stride QKVW.
// ---------------------------------------------------------------------------
__global__ void kv_reduce_kernel(const __half* __restrict__ qkv) {
    int bh = blockIdx.x;             // 0..15
    int b  = bh >> 1, hk = bh & 1;
    int s0 = blockIdx.y * 512;
    __shared__ float pks[8][64];
    __shared__ float vs [8][64];
    int tid = threadIdx.x;
    int m  = tid >> 2;
    int d0 = (tid & 3) * 16;
    float acc[16];
    #pragma unroll
    for (int j = 0; j < 16; j++) acc[j] = 0.f;
    float zacc = 0.f;
    int rr = tid >> 6;               // 0..3
    int cc = tid & 63;
    for (int ss = 0; ss < 512; ss += 8) {
        size_t n = (size_t)b * Sz + s0 + ss;
        pks[rr  ][cc] = d_pk[(n + rr    ) * (HKz*Mz) + hk*Mz + cc];
        pks[rr+4][cc] = d_pk[(n + rr + 4) * (HKz*Mz) + hk*Mz + cc];
        vs [rr  ][cc] = __half2float(qkv[(n + rr    ) * QKVW + 640 + hk*DHz + cc]);
        vs [rr+4][cc] = __half2float(qkv[(n + rr + 4) * QKVW + 640 + hk*DHz + cc]);
        __syncthreads();
        #pragma unroll
        for (int t = 0; t < 8; t++) {
            float pm = pks[t][m];
            zacc += pm;
            #pragma unroll
            for (int j = 0; j < 16; j++) acc[j] += pm * vs[t][d0 + j];
        }
        __syncthreads();
    }
    size_t base = ((size_t)bh * Mz + m) * DHz + d0;
    #pragma unroll
    for (int j = 0; j < 16; j++) atomicAdd(&d_kv[base + j], acc[j]);
    if ((tid & 3) == 0) atomicAdd(&d_z[bh * Mz + m], zacc);
}

// ---------------------------------------------------------------------------
// Attention readout: attn[n, h*64+d] = (pq . kv)/(pq . z + eps) -> d_q (fp16)
// ---------------------------------------------------------------------------
__global__ void attn_kernel() {
    int n0 = blockIdx.x * 32;
    int b  = n0 >> 13;                  // / Sz
    __shared__ float kvs[2][64][64];
    __shared__ float zs [2][64];
    __shared__ float pqs[32][64];
    __shared__ float dens[32];
    int tid = threadIdx.x;
    for (int i = tid; i < 2*64*64; i += 256)
        ((float*)kvs)[i] = d_kv[(size_t)b * (HKz*Mz*DHz) + i];
    for (int i = tid; i < 2*64; i += 256)
        ((float*)zs)[i] = d_z[b * (HKz*Mz) + i];

    for (int h = 0; h < Hz; h++) {
        int hk = h >> 2;
        for (int i = tid; i < 32*64; i += 256) {
            int r = i >> 6, m = i & 63;
            pqs[r][m] = d_pq[(size_t)(n0 + r) * (Hz*Mz) + h*Mz + m];
        }
        __syncthreads();
        if (tid < 32) {
            float s = 0.f;
            #pragma unroll 8
            for (int m = 0; m < 64; m++) s += pqs[tid][m] * zs[hk][m];
            dens[tid] = s + 1e-6f;
        }
        __syncthreads();
        int r = tid >> 3, d0 = (tid & 7) * 8;
        float acc[8];
        #pragma unroll
        for (int j = 0; j < 8; j++) acc[j] = 0.f;
        #pragma unroll 8
        for (int m = 0; m < 64; m++) {
            float p = pqs[r][m];
            float4 k0 = *(float4*)&kvs[hk][m][d0];
            float4 k1 = *(float4*)&kvs[hk][m][d0 + 4];
            acc[0] += p*k0.x; acc[1] += p*k0.y; acc[2] += p*k0.z; acc[3] += p*k0.w;
            acc[4] += p*k1.x; acc[5] += p*k1.y; acc[6] += p*k1.z; acc[7] += p*k1.w;
        }
        float inv = 1.f / dens[r];
        size_t base = (size_t)(n0 + r) * (Hz*DHz) + h*DHz + d0;
        #pragma unroll
        for (int j = 0; j < 8; j++)
            d_q[base + j] = __float2half(acc[j] * inv);
        __syncthreads();
    }
}

// ---------------------------------------------------------------------------
// Mean pool partials
// ---------------------------------------------------------------------------
__global__ void pool_kernel() {
    int b = blockIdx.x;
    int d = blockIdx.y * 256 + threadIdx.x;
    size_t base = ((size_t)b * Sz + blockIdx.z * 512) * Dz + d;
    float s = 0.f;
    #pragma unroll 4
    for (int i = 0; i < 512; i++) s += d_x[base + (size_t)i * Dz];
    atomicAdd(&d_pool[b * Dz + d], s);
}

// ---------------------------------------------------------------------------
// Head
// ---------------------------------------------------------------------------
__global__ void head_kernel(const float* __restrict__ Wc,
                            const float* __restrict__ bc,
                            float* __restrict__ out) {
    int w = threadIdx.x >> 5, lane = threadIdx.x & 31;
    int b = w >> 1, c = w & 1;
    float s = 0.f;
    for (int d = lane; d < Dz; d += 32)
        s += d_pool[b * Dz + d] * Wc[d * NCLSz + c];
    #pragma unroll
    for (int o = 16; o; o >>= 1) s += __shfl_xor_sync(0xffffffffu, s, o);
    if (lane == 0) out[b * NCLSz + c] = s / (float)Sz + bc[c];
}

// ---------------------------------------------------------------------------
// Launch (graph-capturable: kernel launches only)
// ---------------------------------------------------------------------------
extern "C" void kernel_launch(void* const* d_in, const int* in_sizes, int n_in,
                              void* d_out, int out_size) {
    const int*   ids  = (const int*)  d_in[0];
    const float* emb  = (const float*)d_in[1];
    const float* Wq   = (const float*)d_in[2];
    const float* Wk   = (const float*)d_in[3];
    const float* Wv   = (const float*)d_in[4];
    const float* Wphi = (const float*)d_in[5];
    const float* Wo   = (const float*)d_in[6];
    const float* g1   = (const float*)d_in[7];
    const float* g2   = (const float*)d_in[8];
    const float* Wg   = (const float*)d_in[9];
    const float* Wu   = (const float*)d_in[10];
    const float* Wd   = (const float*)d_in[11];
    const float* Wc   = (const float*)d_in[12];
    const float* bc   = (const float*)d_in[13];
    float* out = (float*)d_out;

    float *px, *ppq, *ppk;
    __half *ph, *pq_, *pqkv, *pt1, *pwt;
    cudaGetSymbolAddress((void**)&px,   d_x);
    cudaGetSymbolAddress((void**)&ph,   d_h);
    cudaGetSymbolAddress((void**)&pq_,  d_q);
    cudaGetSymbolAddress((void**)&pqkv, d_qkv);
    cudaGetSymbolAddress((void**)&ppq,  d_pq);
    cudaGetSymbolAddress((void**)&ppk,  d_pk);
    cudaGetSymbolAddress((void**)&pt1,  d_t1);
    cudaGetSymbolAddress((void**)&pwt,  d_wt);

    __half* tQKV = pwt;                 // [768,512] fused
    __half* tWk  = pwt + 262144;        // rows 512-639
    __half* tWv  = pwt + 327680;        // rows 640-767
    __half* tWo  = pwt + 393216;
    __half* tWg  = pwt + 655360;
    __half* tWu  = pwt + 1703936;
    __half* tWd  = pwt + 2752512;

    const int SMEM_H = (NSTG * ASTGh + NSTG * BSTGh) * 2;   // 92160 B
    cudaFuncSetAttribute(hgemm_kernel<0>, cudaFuncAttributeMaxDynamicSharedMemorySize, SMEM_H);
    cudaFuncSetAttribute(hgemm_kernel<1>, cudaFuncAttributeMaxDynamicSharedMemorySize, SMEM_H);
    cudaFuncSetAttribute(hgemm_kernel<2>, cudaFuncAttributeMaxDynamicSharedMemorySize, SMEM_H);
    cudaFuncSetAttribute(hgemm_kernel<3>, cudaFuncAttributeMaxDynamicSharedMemorySize, SMEM_H);

    // 0. transpose+convert weights to fp16 [N,K] (QKV packed as [768,512])
    transpose_h_kernel<<<dim3(Dz/32,   Dz/32),   dim3(32,8)>>>(Wq, tQKV, Dz,  Dz);
    transpose_h_kernel<<<dim3(128/32,  Dz/32),   dim3(32,8)>>>(Wk, tWk,  Dz,  128);
    transpose_h_kernel<<<dim3(128/32,  Dz/32),   dim3(32,8)>>>(Wv, tWv,  Dz,  128);
    transpose_h_kernel<<<dim3(Dz/32,   Dz/32),   dim3(32,8)>>>(Wo, tWo,  Dz,  Dz);
    transpose_h_kernel<<<dim3(DFFz/32, Dz/32),   dim3(32,8)>>>(Wg, tWg,  Dz,  DFFz);
    transpose_h_kernel<<<dim3(DFFz/32, Dz/32),   dim3(32,8)>>>(Wu, tWu,  Dz,  DFFz);
    transpose_h_kernel<<<dim3(Dz/32,   DFFz/32), dim3(32,8)>>>(Wd, tWd,  DFFz, Dz);

    // 1. zero accumulators
    zero_scratch_kernel<<<(Bz*HKz*Mz*DHz + 255)/256, 256>>>();
    // 2. embed + rmsnorm (h fp16)
    embed_rms_kernel<<<Nz, 128>>>(ids, emb, g1);
    // 3. fused QKV projection -> d_qkv [N,768]
    hgemm_kernel<0><<<dim3(QKVW/128, Nz/256), 256, SMEM_H>>>(ph, tQKV, pqkv, Dz, QKVW);
    // 4-5. Laplacian feature maps (q at col 0, k at col 512 of qkv)
    phi_kernel<<<dim3(Nz/64, Hz),  256>>>(pqkv,       Wphi, ppq, QKVW, Hz*Mz);
    phi_kernel<<<dim3(Nz/64, HKz), 256>>>(pqkv + 512, Wphi, ppk, QKVW, HKz*Mz);
    // 6. global state (v at col 640 of qkv)
    kv_reduce_kernel<<<dim3(Bz*HKz, 16), 256>>>(pqkv);
    // 7. attention readout (into d_q, fp16)
    attn_kernel<<<Nz/32, 256>>>();
    // 8. x += attn @ Wo
    hgemm_kernel<1><<<dim3(Dz/128, Nz/256), 256, SMEM_H>>>(pq_, tWo, px, Dz, Dz);
    // 9. h2 = rmsnorm(x, g2) (fp16)
    rms_kernel<<<Nz, 128>>>(g2);
    // 10. t1 = silu(h2 @ Wg)  (fp16)
    hgemm_kernel<2><<<dim3(DFFz/128, Nz/256), 256, SMEM_H>>>(ph, tWg, pt1, Dz, DFFz);
    // 11. t1 = half(t1 * (h2 @ Wu))
    hgemm_kernel<3><<<dim3(DFFz/128, Nz/256), 256, SMEM_H>>>(ph, tWu, pt1, Dz, DFFz);
    // 12. x += t1 @ Wd
    hgemm_kernel<1><<<dim3(Dz/128, Nz/256), 256, SMEM_H>>>(pt1, tWd, px, DFFz, Dz);
    // 13. mean pool
    pool_kernel<<<dim3(Bz, Dz/256, Sz/512), 256>>>();
    // 14. head
    head_kernel<<<1, 512>>>(Wc, bc, out);
}

// round 13
// speedup vs baseline: 3.2946x; 1.0895x over previous
#include <cuda_runtime.h>
#include <cuda_fp16.h>
#include <math.h>
#include <stdint.h>

// ---------------------------------------------------------------------------
// Problem constants
// ---------------------------------------------------------------------------
#define Bz    8
#define Sz    8192
#define Nz    (Bz*Sz)          // 65536 tokens
#define Dz    512
#define Hz    8
#define HKz   2
#define DHz   64
#define Mz    64
#define DFFz  2048
#define NCLSz 2
#define QKVW  768              // fused QKV output width

// ---------------------------------------------------------------------------
// Scratch (device globals; no allocations allowed)
// ---------------------------------------------------------------------------
__device__ float  d_x [Nz*Dz];                          // residual (fp32)
__device__ __align__(16) __half d_h [Nz*Dz];            // rmsnorm out (fp16)
__device__ __align__(16) __half d_q [Nz*Dz];            // attn out (fp16)
__device__ __align__(16) __half d_qkv[(size_t)Nz*QKVW]; // fused q|k|v (fp16)
__device__ float  d_pq[Nz*Hz*Mz];
__device__ float  d_pk[Nz*HKz*Mz];
__device__ __align__(16) __half d_t1[(size_t)Nz*DFFz];  // FFN intermediate
__device__ float  d_kv[Bz*HKz*Mz*DHz];
__device__ float  d_z [Bz*HKz*Mz];
__device__ float  d_pool[Bz*Dz];
// fp16 transposed weights [N,K] packed. Rows of the fused QKV matrix [768,512]:
// Wq^T rows 0-511 @0, Wk^T rows 512-639 @262144, Wv^T rows 640-767 @327680.
// Then Wo@393216(262144) Wg@655360(1048576) Wu@1703936(1048576) Wd@2752512(1048576)
__device__ __align__(16) __half d_wt[3801088];

// ---------------------------------------------------------------------------
// helpers
// ---------------------------------------------------------------------------
__device__ __forceinline__ uint32_t smem_u32(const void* p) {
    uint32_t a;
    asm("{ .reg .u64 t; cvta.to.shared.u64 t, %1; cvt.u32.u64 %0, t; }"
        : "=r"(a) : "l"(p));
    return a;
}
__device__ __forceinline__ void cp16(uint32_t s, const void* g) {
    asm volatile("cp.async.cg.shared.global [%0], [%1], 16;" :: "r"(s), "l"(g));
}
#define CP_COMMIT() asm volatile("cp.async.commit_group;" ::: "memory")
__device__ __forceinline__ void ldsm4(uint32_t& r0, uint32_t& r1,
                                      uint32_t& r2, uint32_t& r3, uint32_t addr) {
    asm volatile("ldmatrix.sync.aligned.m8n8.x4.shared.b16 {%0,%1,%2,%3}, [%4];"
                 : "=r"(r0), "=r"(r1), "=r"(r2), "=r"(r3) : "r"(addr));
}

// ---------------------------------------------------------------------------
__global__ void zero_scratch_kernel() {
    int i = blockIdx.x * 256 + threadIdx.x;
    if (i < Bz*HKz*Mz*DHz) d_kv[i]   = 0.f;
    if (i < Bz*HKz*Mz)     d_z[i]    = 0.f;
    if (i < Bz*Dz)         d_pool[i] = 0.f;
}

// ---------------------------------------------------------------------------
// Weight transpose+convert: W [K,N] fp32 -> Wt [N,K] fp16
// ---------------------------------------------------------------------------
__global__ void transpose_h_kernel(const float* __restrict__ W,
                                   __half* __restrict__ Wt, int K, int N) {
    __shared__ float t[32][33];
    int n0 = blockIdx.x * 32, k0 = blockIdx.y * 32;
    int tx = threadIdx.x, ty = threadIdx.y;
    #pragma unroll
    for (int i = 0; i < 32; i += 8)
        t[ty + i][tx] = W[(size_t)(k0 + ty + i) * N + n0 + tx];
    __syncthreads();
    #pragma unroll
    for (int i = 0; i < 32; i += 8)
        Wt[(size_t)(n0 + ty + i) * K + k0 + tx] = __float2half(t[tx][ty + i]);
}

// ---------------------------------------------------------------------------
// Embedding gather + RMSNorm (x fp32, h fp16)
// ---------------------------------------------------------------------------
__global__ void embed_rms_kernel(const int* __restrict__ ids,
                                 const float* __restrict__ emb,
                                 const float* __restrict__ g) {
    int n   = blockIdx.x;
    int tid = threadIdx.x;
    int id  = ids[n];
    float4 v = *(const float4*)&emb[(size_t)id * Dz + tid * 4];
    float ss = v.x*v.x + v.y*v.y + v.z*v.z + v.w*v.w;
    __shared__ float red[4];
    #pragma unroll
    for (int o = 16; o; o >>= 1) ss += __shfl_xor_sync(0xffffffffu, ss, o);
    if ((tid & 31) == 0) red[tid >> 5] = ss;
    __syncthreads();
    float tot = red[0] + red[1] + red[2] + red[3];
    float scale = rsqrtf(tot / (float)Dz + 1e-6f);
    *(float4*)&d_x[(size_t)n * Dz + tid * 4] = v;
    float4 gv = *(const float4*)&g[tid * 4];
    __half2 h0 = __floats2half2_rn(v.x*scale*gv.x, v.y*scale*gv.y);
    __half2 h1 = __floats2half2_rn(v.z*scale*gv.z, v.w*scale*gv.w);
    *(__half2*)&d_h[(size_t)n * Dz + tid * 4]     = h0;
    *(__half2*)&d_h[(size_t)n * Dz + tid * 4 + 2] = h1;
}

// RMSNorm of d_x into d_h (fp16)
__global__ void rms_kernel(const float* __restrict__ g) {
    int n   = blockIdx.x;
    int tid = threadIdx.x;
    float4 v = *(const float4*)&d_x[(size_t)n * Dz + tid * 4];
    float ss = v.x*v.x + v.y*v.y + v.z*v.z + v.w*v.w;
    __shared__ float red[4];
    #pragma unroll
    for (int o = 16; o; o >>= 1) ss += __shfl_xor_sync(0xffffffffu, ss, o);
    if ((tid & 31) == 0) red[tid >> 5] = ss;
    __syncthreads();
    float tot = red[0] + red[1] + red[2] + red[3];
    float scale = rsqrtf(tot / (float)Dz + 1e-6f);
    float4 gv = *(const float4*)&g[tid * 4];
    __half2 h0 = __floats2half2_rn(v.x*scale*gv.x, v.y*scale*gv.y);
    __half2 h1 = __floats2half2_rn(v.z*scale*gv.z, v.w*scale*gv.w);
    *(__half2*)&d_h[(size_t)n * Dz + tid * 4]     = h0;
    *(__half2*)&d_h[(size_t)n * Dz + tid * 4 + 2] = h1;
}

// ---------------------------------------------------------------------------
// FP16 mma.sync GEMM, ldmatrix fragment loads.
// Block tile 128x128, 128 threads (4 warps, 2x2 of 64x64 warp tiles), BK=32,
// 4-stage cp.async pipeline, m16n8k16 fp16 -> fp32 accum.
// 80KB smem/CTA, ~200 regs -> 2 CTAs/SM co-resident (independent pipelines).
// A [Mr,K] fp16 row-major, Bt [Nc,K] fp16 row-major.
// MODE 0: Chalf = acc; 1: Cfloat += acc; 2: Chalf = silu(acc);
// 3: Chalf = half(half2float(Chalf) * acc).
// grid (Nc/128, Mr/128), block 128, dynamic smem 81920 B.
// ---------------------------------------------------------------------------
#define AKP 40               // halves per A smem row (32 k + 8 pad = 80 B)
#define BKP 40               // halves per B smem row
#define ASTGh (128*AKP)      // 5120 halves / stage
#define BSTGh (128*BKP)      // 5120 halves / stage
#define NSTG  4

template<int MODE>
__global__ void __launch_bounds__(128)
hgemm_kernel(const __half* __restrict__ A, const __half* __restrict__ Bt,
             void* __restrict__ Cv, int K, int Nc) {
    extern __shared__ __half hsm[];
    __half* As = hsm;                      // [4][128][AKP]
    __half* Bs = hsm + NSTG * ASTGh;       // [4][128][BKP]
    uint32_t uA = smem_u32(As);
    uint32_t uB = smem_u32(Bs);

    int tid  = threadIdx.x;
    int lane = tid & 31;
    int warp = tid >> 5;
    int wm  = (warp >> 1) * 64;            // 0,64
    int wn  = (warp & 1) * 64;             // 0,64
    int gid = lane >> 2;                   // 0..7
    int tig = lane & 3;                    // 0..3

    // ldmatrix lane-address components
    int aRowL = (lane & 7) + ((lane >> 3) & 1) * 8;  // row within 16-row A tile
    int aColL = (lane >> 4) * 8;                     // k offset 0/8
    int jj    = lane >> 3;                           // B matrix index 0..3
    int bRowL = ((jj >> 1) * 8) + (lane & 7);        // row within 16-row B pair
    int bColL = (jj & 1) * 8;                        // k offset 0/8

    const __half* Ablk = A  + (size_t)(blockIdx.y * 128) * K;
    const __half* Bblk = Bt + (size_t)(blockIdx.x * 128) * K;

    float acc[4][8][4];
    #pragma unroll
    for (int i = 0; i < 4; i++)
        #pragma unroll
        for (int j = 0; j < 8; j++)
            #pragma unroll
            for (int r = 0; r < 4; r++) acc[i][j][r] = 0.f;

    int cr = tid >> 2;                     // 0..31 copy row
    int cc = tid & 3;                      // 0..3 chunk (8 halves)

    int NS = K >> 5;                       // K/32 stages

    auto load_stage = [&](int s, int buf) {
        int k0 = s << 5;
        uint32_t ab = uA + (uint32_t)buf * (ASTGh * 2);
        uint32_t bb = uB + (uint32_t)buf * (BSTGh * 2);
        #pragma unroll
        for (int t = 0; t < 4; t++) {      // A: 128 rows, 32/pass
            int m = cr + t * 32;
            cp16(ab + (uint32_t)(m * (AKP*2) + cc * 16),
                 Ablk + (size_t)m * K + k0 + cc * 8);
        }
        #pragma unroll
        for (int t = 0; t < 4; t++) {      // B: 128 rows
            int n = cr + t * 32;
            cp16(bb + (uint32_t)(n * (BKP*2) + cc * 16),
                 Bblk + (size_t)n * K + k0 + cc * 8);
        }
        CP_COMMIT();
    };

    load_stage(0, 0);
    load_stage(1, 1);
    load_stage(2, 2);

    for (int s = 0; s < NS; s++) {
        int bufC = s & 3;
        if (s + 3 < NS) {
            load_stage(s + 3, (s + 3) & 3);
            asm volatile("cp.async.wait_group 3;" ::: "memory");
        } else if (s + 2 < NS) {
            asm volatile("cp.async.wait_group 2;" ::: "memory");
        } else if (s + 1 < NS) {
            asm volatile("cp.async.wait_group 1;" ::: "memory");
        } else {
            asm volatile("cp.async.wait_group 0;" ::: "memory");
        }
        __syncthreads();

        uint32_t aBase = uA + (uint32_t)bufC * (ASTGh * 2);
        uint32_t bBase = uB + (uint32_t)bufC * (BSTGh * 2);
        #pragma unroll
        for (int kk = 0; kk < 32; kk += 16) {
            uint32_t a[4][4];
            #pragma unroll
            for (int mt = 0; mt < 4; mt++) {
                uint32_t addr = aBase +
                    (uint32_t)((wm + mt * 16 + aRowL) * AKP + kk + aColL) * 2;
                ldsm4(a[mt][0], a[mt][1], a[mt][2], a[mt][3], addr);
            }
            uint32_t b[8][2];
            #pragma unroll
            for (int p = 0; p < 4; p++) {  // nt pair (2p, 2p+1)
                uint32_t addr = bBase +
                    (uint32_t)((wn + p * 16 + bRowL) * BKP + kk + bColL) * 2;
                ldsm4(b[2*p][0], b[2*p][1], b[2*p+1][0], b[2*p+1][1], addr);
            }
            #pragma unroll
            for (int mt = 0; mt < 4; mt++)
                #pragma unroll
                for (int nt = 0; nt < 8; nt++) {
                    asm volatile(
                        "mma.sync.aligned.m16n8k16.row.col.f32.f16.f16.f32 "
                        "{%0,%1,%2,%3}, {%4,%5,%6,%7}, {%8,%9}, {%0,%1,%2,%3};"
                        : "+f"(acc[mt][nt][0]), "+f"(acc[mt][nt][1]),
                          "+f"(acc[mt][nt][2]), "+f"(acc[mt][nt][3])
                        : "r"(a[mt][0]), "r"(a[mt][1]), "r"(a[mt][2]), "r"(a[mt][3]),
                          "r"(b[nt][0]), "r"(b[nt][1]));
                }
        }
        __syncthreads();
    }

    // epilogue: c0,c1 = row gid cols 2tig,2tig+1; c2,c3 = row gid+8
    int rowBase = blockIdx.y * 128 + wm;
    int colBase = blockIdx.x * 128 + wn;
    #pragma unroll
    for (int mt = 0; mt < 4; mt++) {
        #pragma unroll
        for (int nt = 0; nt < 8; nt++) {
            #pragma unroll
            for (int half_ = 0; half_ < 2; half_++) {
                int row = rowBase + mt * 16 + gid + half_ * 8;
                int col = colBase + nt * 8 + tig * 2;
                size_t off = (size_t)row * Nc + col;
                float v0 = acc[mt][nt][half_ * 2 + 0];
                float v1 = acc[mt][nt][half_ * 2 + 1];
                if (MODE == 0) {
                    *(__half2*)((__half*)Cv + off) = __floats2half2_rn(v0, v1);
                } else if (MODE == 1) {
                    float* C = (float*)Cv;
                    float2 c = *(float2*)&C[off];
                    c.x += v0; c.y += v1;
                    *(float2*)&C[off] = c;
                } else if (MODE == 2) {
                    v0 = v0 / (1.f + expf(-v0));
                    v1 = v1 / (1.f + expf(-v1));
                    *(__half2*)((__half*)Cv + off) = __floats2half2_rn(v0, v1);
                } else {
                    __half2 c = *(__half2*)((__half*)Cv + off);
                    float2 cf = __half22float2(c);
                    *(__half2*)((__half*)Cv + off) =
                        __floats2half2_rn(v0 * cf.x, v1 * cf.y);
                }
            }
        }
    }
}

// ---------------------------------------------------------------------------
// phi projection: out[n, h*64+m] = exp(-|sum_d in[n*ldin + h*64+d]*Wphi[d,m]|)
// ---------------------------------------------------------------------------
__global__ void phi_kernel(const __half* __restrict__ in,
                           const float* __restrict__ Wphi,
                           float* __restrict__ out, int ldin, int ldout) {
    int h  = blockIdx.y;
    int n0 = blockIdx.x * 64;
    __shared__ float Ws[64][65];
    __shared__ float Qs[64][65];
    int tid = threadIdx.x;
    for (int i = tid; i < 4096; i += 256) {
        int r = i >> 6, c = i & 63;
        Ws[r][c] = Wphi[i];
        Qs[r][c] = __half2float(in[(size_t)(n0 + r) * ldin + h * 64 + c]);
    }
    __syncthreads();
    int r  = tid >> 2;
    int m0 = (tid & 3) * 16;
    float acc[16];
    #pragma unroll
    for (int j = 0; j < 16; j++) acc[j] = 0.f;
    #pragma unroll 8
    for (int d = 0; d < 64; d++) {
        float qv = Qs[r][d];
        #pragma unroll
        for (int j = 0; j < 16; j++) acc[j] += qv * Ws[d][m0 + j];
    }
    size_t base = (size_t)(n0 + r) * ldout + h * 64 + m0;
    #pragma unroll
    for (int j = 0; j < 16; j++)
        out[base + j] = expf(-fabsf(acc[j]));
}

// ---------------------------------------------------------------------------
// kv state reduction: kv[b,hk,m,d] = sum_s pk * v;  z[b,hk,m] = sum_s pk
// ---------------------------------------------------------------------------
__global__ void kv_reduce_kernel(const __half* __restrict__ qkv) {
    int bh = blockIdx.x;             // 0..15
    int b  = bh >> 1, hk = bh & 1;
    int s0 = blockIdx.y * 512;
    __shared__ float pks[8][64];
    __shared__ float vs [8][64];
    int tid = threadIdx.x;
    int m  = tid >> 2;
    int d0 = (tid & 3) * 16;
    float acc[16];
    #pragma unroll
    for (int j = 0; j < 16; j++) acc[j] = 0.f;
    float zacc = 0.f;
    int rr = tid >> 6;               // 0..3
    int cc = tid & 63;
    for (int ss = 0; ss < 512; ss += 8) {
        size_t n = (size_t)b * Sz + s0 + ss;
        pks[rr  ][cc] = d_pk[(n + rr    ) * (HKz*Mz) + hk*Mz + cc];
        pks[rr+4][cc] = d_pk[(n + rr + 4) * (HKz*Mz) + hk*Mz + cc];
        vs [rr  ][cc] = __half2float(qkv[(n + rr    ) * QKVW + 640 + hk*DHz + cc]);
        vs [rr+4][cc] = __half2float(qkv[(n + rr + 4) * QKVW + 640 + hk*DHz + cc]);
        __syncthreads();
        #pragma unroll
        for (int t = 0; t < 8; t++) {
            float pm = pks[t][m];
            zacc += pm;
            #pragma unroll
            for (int j = 0; j < 16; j++) acc[j] += pm * vs[t][d0 + j];
        }
        __syncthreads();
    }
    size_t base = ((size_t)bh * Mz + m) * DHz + d0;
    #pragma unroll
    for (int j = 0; j < 16; j++) atomicAdd(&d_kv[base + j], acc[j]);
    if ((tid & 3) == 0) atomicAdd(&d_z[bh * Mz + m], zacc);
}

// ---------------------------------------------------------------------------
// Attention readout: attn[n, h*64+d] = (pq . kv)/(pq . z + eps) -> d_q (fp16)
// ---------------------------------------------------------------------------
__global__ void attn_kernel() {
    int n0 = blockIdx.x * 32;
    int b  = n0 >> 13;                  // / Sz
    __shared__ float kvs[2][64][64];
    __shared__ float zs [2][64];
    __shared__ float pqs[32][64];
    __shared__ float dens[32];
    int tid = threadIdx.x;
    for (int i = tid; i < 2*64*64; i += 256)
        ((float*)kvs)[i] = d_kv[(size_t)b * (HKz*Mz*DHz) + i];
    for (int i = tid; i < 2*64; i += 256)
        ((float*)zs)[i] = d_z[b * (HKz*Mz) + i];

    for (int h = 0; h < Hz; h++) {
        int hk = h >> 2;
        for (int i = tid; i < 32*64; i += 256) {
            int r = i >> 6, m = i & 63;
            pqs[r][m] = d_pq[(size_t)(n0 + r) * (Hz*Mz) + h*Mz + m];
        }
        __syncthreads();
        if (tid < 32) {
            float s = 0.f;
            #pragma unroll 8
            for (int m = 0; m < 64; m++) s += pqs[tid][m] * zs[hk][m];
            dens[tid] = s + 1e-6f;
        }
        __syncthreads();
        int r = tid >> 3, d0 = (tid & 7) * 8;
        float acc[8];
        #pragma unroll
        for (int j = 0; j < 8; j++) acc[j] = 0.f;
        #pragma unroll 8
        for (int m = 0; m < 64; m++) {
            float p = pqs[r][m];
            float4 k0 = *(float4*)&kvs[hk][m][d0];
            float4 k1 = *(float4*)&kvs[hk][m][d0 + 4];
            acc[0] += p*k0.x; acc[1] += p*k0.y; acc[2] += p*k0.z; acc[3] += p*k0.w;
            acc[4] += p*k1.x; acc[5] += p*k1.y; acc[6] += p*k1.z; acc[7] += p*k1.w;
        }
        float inv = 1.f / dens[r];
        size_t base = (size_t)(n0 + r) * (Hz*DHz) + h*DHz + d0;
        #pragma unroll
        for (int j = 0; j < 8; j++)
            d_q[base + j] = __float2half(acc[j] * inv);
        __syncthreads();
    }
}

// ---------------------------------------------------------------------------
// Mean pool partials
// ---------------------------------------------------------------------------
__global__ void pool_kernel() {
    int b = blockIdx.x;
    int d = blockIdx.y * 256 + threadIdx.x;
    size_t base = ((size_t)b * Sz + blockIdx.z * 512) * Dz + d;
    float s = 0.f;
    #pragma unroll 4
    for (int i = 0; i < 512; i++) s += d_x[base + (size_t)i * Dz];
    atomicAdd(&d_pool[b * Dz + d], s);
}

// ---------------------------------------------------------------------------
// Head
// ---------------------------------------------------------------------------
__global__ void head_kernel(const float* __restrict__ Wc,
                            const float* __restrict__ bc,
                            float* __restrict__ out) {
    int w = threadIdx.x >> 5, lane = threadIdx.x & 31;
    int b = w >> 1, c = w & 1;
    float s = 0.f;
    for (int d = lane; d < Dz; d += 32)
        s += d_pool[b * Dz + d] * Wc[d * NCLSz + c];
    #pragma unroll
    for (int o = 16; o; o >>= 1) s += __shfl_xor_sync(0xffffffffu, s, o);
    if (lane == 0) out[b * NCLSz + c] = s / (float)Sz + bc[c];
}

// ---------------------------------------------------------------------------
// Launch (graph-capturable: kernel launches only).
// Order puts the QKV GEMM at launch index 5 so ncu (-s 5 -c 1) profiles it.
// ---------------------------------------------------------------------------
extern "C" void kernel_launch(void* const* d_in, const int* in_sizes, int n_in,
                              void* d_out, int out_size) {
    const int*   ids  = (const int*)  d_in[0];
    const float* emb  = (const float*)d_in[1];
    const float* Wq   = (const float*)d_in[2];
    const float* Wk   = (const float*)d_in[3];
    const float* Wv   = (const float*)d_in[4];
    const float* Wphi = (const float*)d_in[5];
    const float* Wo   = (const float*)d_in[6];
    const float* g1   = (const float*)d_in[7];
    const float* g2   = (const float*)d_in[8];
    const float* Wg   = (const float*)d_in[9];
    const float* Wu   = (const float*)d_in[10];
    const float* Wd   = (const float*)d_in[11];
    const float* Wc   = (const float*)d_in[12];
    const float* bc   = (const float*)d_in[13];
    float* out = (float*)d_out;

    float *px, *ppq, *ppk;
    __half *ph, *pq_, *pqkv, *pt1, *pwt;
    cudaGetSymbolAddress((void**)&px,   d_x);
    cudaGetSymbolAddress((void**)&ph,   d_h);
    cudaGetSymbolAddress((void**)&pq_,  d_q);
    cudaGetSymbolAddress((void**)&pqkv, d_qkv);
    cudaGetSymbolAddress((void**)&ppq,  d_pq);
    cudaGetSymbolAddress((void**)&ppk,  d_pk);
    cudaGetSymbolAddress((void**)&pt1,  d_t1);
    cudaGetSymbolAddress((void**)&pwt,  d_wt);

    __half* tQKV = pwt;                 // [768,512] fused
    __half* tWk  = pwt + 262144;        // rows 512-639
    __half* tWv  = pwt + 327680;        // rows 640-767
    __half* tWo  = pwt + 393216;
    __half* tWg  = pwt + 655360;
    __half* tWu  = pwt + 1703936;
    __half* tWd  = pwt + 2752512;

    const int SMEM_H = (NSTG * ASTGh + NSTG * BSTGh) * 2;   // 81920 B
    cudaFuncSetAttribute(hgemm_kernel<0>, cudaFuncAttributeMaxDynamicSharedMemorySize, SMEM_H);
    cudaFuncSetAttribute(hgemm_kernel<1>, cudaFuncAttributeMaxDynamicSharedMemorySize, SMEM_H);
    cudaFuncSetAttribute(hgemm_kernel<2>, cudaFuncAttributeMaxDynamicSharedMemorySize, SMEM_H);
    cudaFuncSetAttribute(hgemm_kernel<3>, cudaFuncAttributeMaxDynamicSharedMemorySize, SMEM_H);

    // launches 0-4: QKV weight transposes + zero + embed
    transpose_h_kernel<<<dim3(Dz/32,  Dz/32), dim3(32,8)>>>(Wq, tQKV, Dz, Dz);
    transpose_h_kernel<<<dim3(128/32, Dz/32), dim3(32,8)>>>(Wk, tWk,  Dz, 128);
    transpose_h_kernel<<<dim3(128/32, Dz/32), dim3(32,8)>>>(Wv, tWv,  Dz, 128);
    zero_scratch_kernel<<<(Bz*HKz*Mz*DHz + 255)/256, 256>>>();
    embed_rms_kernel<<<Nz, 128>>>(ids, emb, g1);
    // launch 5 (ncu capture slot): fused QKV projection -> d_qkv [N,768]
    hgemm_kernel<0><<<dim3(QKVW/128, Nz/128), 128, SMEM_H>>>(ph, tQKV, pqkv, Dz, QKVW);
    // remaining weight transposes (overlap-free, cheap)
    transpose_h_kernel<<<dim3(Dz/32,   Dz/32),   dim3(32,8)>>>(Wo, tWo, Dz,   Dz);
    transpose_h_kernel<<<dim3(DFFz/32, Dz/32),   dim3(32,8)>>>(Wg, tWg, Dz,   DFFz);
    transpose_h_kernel<<<dim3(DFFz/32, Dz/32),   dim3(32,8)>>>(Wu, tWu, Dz,   DFFz);
    transpose_h_kernel<<<dim3(Dz/32,   DFFz/32), dim3(32,8)>>>(Wd, tWd, DFFz, Dz);
    // Laplacian feature maps (q at col 0, k at col 512 of qkv)
    phi_kernel<<<dim3(Nz/64, Hz),  256>>>(pqkv,       Wphi, ppq, QKVW, Hz*Mz);
    phi_kernel<<<dim3(Nz/64, HKz), 256>>>(pqkv + 512, Wphi, ppk, QKVW, HKz*Mz);
    // global state (v at col 640 of qkv)
    kv_reduce_kernel<<<dim3(Bz*HKz, 16), 256>>>(pqkv);
    // attention readout (into d_q, fp16)
    attn_kernel<<<Nz/32, 256>>>();
    // x += attn @ Wo
    hgemm_kernel<1><<<dim3(Dz/128, Nz/128), 128, SMEM_H>>>(pq_, tWo, px, Dz, Dz);
    // h2 = rmsnorm(x, g2) (fp16)
    rms_kernel<<<Nz, 128>>>(g2);
    // t1 = silu(h2 @ Wg)  (fp16)
    hgemm_kernel<2><<<dim3(DFFz/128, Nz/128), 128, SMEM_H>>>(ph, tWg, pt1, Dz, DFFz);
    // t1 = half(t1 * (h2 @ Wu))
    hgemm_kernel<3><<<dim3(DFFz/128, Nz/128), 128, SMEM_H>>>(ph, tWu, pt1, Dz, DFFz);
    // x += t1 @ Wd
    hgemm_kernel<1><<<dim3(Dz/128, Nz/128), 128, SMEM_H>>>(pt1, tWd, px, DFFz, Dz);
    // mean pool
    pool_kernel<<<dim3(Bz, Dz/256, Sz/512), 256>>>();
    // head
    head_kernel<<<1, 512>>>(Wc, bc, out);
}